// round 3
// baseline (speedup 1.0000x reference)
#include <cuda_runtime.h>

// ---------------------------------------------------------------------------
// SAGAN self-attention, B=4, C=512, H=W=64 (N=4096).
//   Q = f(x)^T  [b][n][256]   (f_w [256,512], f_b)
//   K = g(x)^T  [b][n][256]
//   V = h(x)^T  [b][n][512]
//   out[b][c][i] = sum_j softmax_j(Q_i . K_j) * V[j][c]
// Kernel 1: fused projection GEMM (f,g,h stacked -> 1024 output channels).
// Kernel 2: flash attention (Br=32, Bc=64), fp32 throughout.
// ---------------------------------------------------------------------------

namespace cfg {
constexpr int NPIX = 4096;
constexpr int CIN  = 512;
constexpr int BQ   = 32;    // query rows per CTA
constexpr int BKV  = 64;    // kv rows per tile
constexpr int KST  = 132;   // padded smem stride for K tile (bank spread)

// dynamic smem layout (floats) for attn kernel
constexpr int OFF_Q  = 0;                    // 32*256  = 8192
constexpr int OFF_K  = OFF_Q + cfg::BQ * 256;       // 8192 ; K tile 64*132 = 8448
constexpr int OFF_V  = OFF_K + cfg::BKV * cfg::KST; // 16640; V tile 64*512 = 32768
constexpr int OFF_P  = OFF_V + cfg::BKV * 512;      // 49408; P tile 32*64 = 2048
constexpr int OFF_SC = OFF_P + cfg::BQ * 64;        // 51456; per-row rescale
constexpr int OFF_L  = OFF_SC + cfg::BQ;            // 51488; per-row final l
constexpr int SMEM_FLOATS = OFF_L + cfg::BQ;        // 51520 floats = 206080 B
}  // namespace cfg

// Scratch for projected Q/K/V (allocation-free rule: device globals). 64 MB.
__device__ float g_Q[4 * cfg::NPIX * 256];
__device__ float g_K[4 * cfg::NPIX * 256];
__device__ float g_V[4 * cfg::NPIX * 512];

// ---------------------------------------------------------------------------
// Projection: per batch, Y[n][o] = sum_c W[o][c] * x[b][c][n] + bias[o]
// with o in [0,1024) stacked as [f(256) | g(256) | h(512)].
// Tiles: 128(o) x 128(n) x 16(k), 256 threads, 8x8 per thread.
// Output written transposed into g_Q / g_K / g_V ([b][n][d], d contiguous).
// ---------------------------------------------------------------------------
__global__ __launch_bounds__(256)
void proj_kernel(const float* __restrict__ x,
                 const float* __restrict__ f_w, const float* __restrict__ f_b,
                 const float* __restrict__ g_w, const float* __restrict__ g_b,
                 const float* __restrict__ h_w, const float* __restrict__ h_b)
{
    __shared__ float sW[16][128];   // [k][o]
    __shared__ float sX[16][128];   // [k][n]

    const int t     = threadIdx.x;
    const int nBase = blockIdx.x * 128;
    const int oBase = blockIdx.y * 128;
    const int b     = blockIdx.z;

    const float* Wsrc; const float* Bsrc; int orow0;
    if (oBase < 256)      { Wsrc = f_w; Bsrc = f_b; orow0 = oBase;       }
    else if (oBase < 512) { Wsrc = g_w; Bsrc = g_b; orow0 = oBase - 256; }
    else                  { Wsrc = h_w; Bsrc = h_b; orow0 = oBase - 512; }

    const int tc = t & 15;          // -> o direction
    const int tr = t >> 4;          // -> n direction
    const int o0 = tc * 8;
    const int n0 = tr * 8;

    float acc[8][8];
#pragma unroll
    for (int i = 0; i < 8; i++)
#pragma unroll
        for (int j = 0; j < 8; j++) acc[i][j] = 0.f;

    const int ow = t & 127;
    const int kq = (t >> 7) * 8;    // 0 or 8

    for (int k0 = 0; k0 < cfg::CIN; k0 += 16) {
        __syncthreads();
        // W tile: 128 o x 16 k, store transposed [k][o]
        const float* wp = Wsrc + (size_t)(orow0 + ow) * cfg::CIN + k0 + kq;
        float4 w0 = *(const float4*)(wp);
        float4 w1 = *(const float4*)(wp + 4);
        sW[kq + 0][ow] = w0.x; sW[kq + 1][ow] = w0.y;
        sW[kq + 2][ow] = w0.z; sW[kq + 3][ow] = w0.w;
        sW[kq + 4][ow] = w1.x; sW[kq + 5][ow] = w1.y;
        sW[kq + 6][ow] = w1.z; sW[kq + 7][ow] = w1.w;
        // X tile: 16 k x 128 n (coalesced)
#pragma unroll
        for (int rep = 0; rep < 2; rep++) {
            int s   = t + rep * 256;
            int row = s >> 5;
            int c4  = (s & 31) << 2;
            *(float4*)&sX[row][c4] =
                *(const float4*)(x + ((size_t)(b * cfg::CIN + k0 + row)) * cfg::NPIX
                                 + nBase + c4);
        }
        __syncthreads();
#pragma unroll
        for (int kk = 0; kk < 16; kk++) {
            float4 a0 = *(const float4*)&sW[kk][o0];
            float4 a1 = *(const float4*)&sW[kk][o0 + 4];
            float4 b0 = *(const float4*)&sX[kk][n0];
            float4 b1 = *(const float4*)&sX[kk][n0 + 4];
            float av[8] = {a0.x, a0.y, a0.z, a0.w, a1.x, a1.y, a1.z, a1.w};
            float bv[8] = {b0.x, b0.y, b0.z, b0.w, b1.x, b1.y, b1.z, b1.w};
#pragma unroll
            for (int nn = 0; nn < 8; nn++)
#pragma unroll
                for (int oo = 0; oo < 8; oo++)
                    acc[nn][oo] += bv[nn] * av[oo];
        }
    }

    // epilogue: write to the proper transposed buffer, bias added
    float* dst; int width; int oc0;
    if (oBase < 256)      { dst = g_Q; width = 256; oc0 = oBase;       }
    else if (oBase < 512) { dst = g_K; width = 256; oc0 = oBase - 256; }
    else                  { dst = g_V; width = 512; oc0 = oBase - 512; }

    float bias[8];
#pragma unroll
    for (int oo = 0; oo < 8; oo++) bias[oo] = Bsrc[orow0 + o0 + oo];

#pragma unroll
    for (int nn = 0; nn < 8; nn++) {
        int n = nBase + n0 + nn;
        float* p = dst + ((size_t)(b * cfg::NPIX + n)) * width + oc0 + o0;
        float4 y0 = make_float4(acc[nn][0] + bias[0], acc[nn][1] + bias[1],
                                acc[nn][2] + bias[2], acc[nn][3] + bias[3]);
        float4 y1 = make_float4(acc[nn][4] + bias[4], acc[nn][5] + bias[5],
                                acc[nn][6] + bias[6], acc[nn][7] + bias[7]);
        *(float4*)(p)     = y0;
        *(float4*)(p + 4) = y1;
    }
}

// ---------------------------------------------------------------------------
// Flash attention. grid (128 row-tiles, 4 batches), 256 threads.
// Map A (S/softmax): tr=t/16 -> 2 rows {2tr,2tr+1}; tc=t%16 -> cols {tc+16*s}.
// Map B (PV/output): rg=t/64 -> 8 rows; cg=t%64 -> 8 contiguous dv cols.
// ---------------------------------------------------------------------------
__global__ __launch_bounds__(256, 1)
void attn_kernel(float* __restrict__ out)
{
    extern __shared__ float sm[];
    float* sQ  = sm + cfg::OFF_Q;
    float* sK  = sm + cfg::OFF_K;
    float* sV  = sm + cfg::OFF_V;
    float* sP  = sm + cfg::OFF_P;
    float* sSc = sm + cfg::OFF_SC;
    float* sL  = sm + cfg::OFF_L;

    const int t  = threadIdx.x;
    const int it = blockIdx.x;
    const int b  = blockIdx.y;

    // load Q tile [32][256] (resident for whole kernel)
    const float* Qg = g_Q + ((size_t)(b * cfg::NPIX + it * cfg::BQ)) * 256;
#pragma unroll
    for (int rep = 0; rep < 8; rep++) {
        int s   = t + rep * 256;
        int row = s >> 6;
        int c4  = (s & 63) << 2;
        *(float4*)(sQ + row * 256 + c4) = *(const float4*)(Qg + row * 256 + c4);
    }

    const int tr = t >> 4, tc = t & 15;
    const int rA = tr * 2;
    const int rg = t >> 6, cg = t & 63;
    const int rB = rg * 8;
    const int c0 = cg * 8;

    float m0 = -1e30f, m1 = -1e30f;
    float l0 = 0.f,    l1 = 0.f;
    float O[8][8];
#pragma unroll
    for (int i = 0; i < 8; i++)
#pragma unroll
        for (int j = 0; j < 8; j++) O[i][j] = 0.f;

    for (int jt = 0; jt < cfg::NPIX / cfg::BKV; jt++) {
        float S0[4] = {0.f, 0.f, 0.f, 0.f};
        float S1[4] = {0.f, 0.f, 0.f, 0.f};
        const float* Kg = g_K + ((size_t)(b * cfg::NPIX + jt * cfg::BKV)) * 256;

        // ---- S = Q . K^T over dqk=256, K streamed in two 128-wide halves ----
#pragma unroll
        for (int half = 0; half < 2; half++) {
            __syncthreads();   // prev readers of sK / prev PV done
#pragma unroll
            for (int rep = 0; rep < 8; rep++) {
                int s   = t + rep * 256;
                int row = s >> 5;
                int c4  = (s & 31) << 2;
                *(float4*)(sK + row * cfg::KST + c4) =
                    *(const float4*)(Kg + row * 256 + half * 128 + c4);
            }
            __syncthreads();
            const float* q0p = sQ + (rA + 0) * 256 + half * 128;
            const float* q1p = sQ + (rA + 1) * 256 + half * 128;
#pragma unroll 4
            for (int k4 = 0; k4 < 32; k4++) {
                float4 q0 = *(const float4*)(q0p + k4 * 4);
                float4 q1 = *(const float4*)(q1p + k4 * 4);
#pragma unroll
                for (int s2 = 0; s2 < 4; s2++) {
                    float4 kv = *(const float4*)(sK + (tc + 16 * s2) * cfg::KST + k4 * 4);
                    S0[s2] += q0.x * kv.x; S0[s2] += q0.y * kv.y;
                    S0[s2] += q0.z * kv.z; S0[s2] += q0.w * kv.w;
                    S1[s2] += q1.x * kv.x; S1[s2] += q1.y * kv.y;
                    S1[s2] += q1.z * kv.z; S1[s2] += q1.w * kv.w;
                }
            }
        }

        // ---- online softmax update (map A); P -> sP, rescale -> sSc ----
        {
            float rm = fmaxf(fmaxf(S0[0], S0[1]), fmaxf(S0[2], S0[3]));
            rm = fmaxf(rm, __shfl_xor_sync(0xffffffffu, rm, 1));
            rm = fmaxf(rm, __shfl_xor_sync(0xffffffffu, rm, 2));
            rm = fmaxf(rm, __shfl_xor_sync(0xffffffffu, rm, 4));
            rm = fmaxf(rm, __shfl_xor_sync(0xffffffffu, rm, 8));
            float mn = fmaxf(m0, rm);
            float sc = __expf(m0 - mn);
            float p0 = __expf(S0[0] - mn), p1 = __expf(S0[1] - mn);
            float p2 = __expf(S0[2] - mn), p3 = __expf(S0[3] - mn);
            float rs = (p0 + p1) + (p2 + p3);
            rs += __shfl_xor_sync(0xffffffffu, rs, 1);
            rs += __shfl_xor_sync(0xffffffffu, rs, 2);
            rs += __shfl_xor_sync(0xffffffffu, rs, 4);
            rs += __shfl_xor_sync(0xffffffffu, rs, 8);
            l0 = l0 * sc + rs;
            m0 = mn;
            if (tc == 0) sSc[rA] = sc;
            sP[rA * 64 + tc     ] = p0;
            sP[rA * 64 + tc + 16] = p1;
            sP[rA * 64 + tc + 32] = p2;
            sP[rA * 64 + tc + 48] = p3;
        }
        {
            float rm = fmaxf(fmaxf(S1[0], S1[1]), fmaxf(S1[2], S1[3]));
            rm = fmaxf(rm, __shfl_xor_sync(0xffffffffu, rm, 1));
            rm = fmaxf(rm, __shfl_xor_sync(0xffffffffu, rm, 2));
            rm = fmaxf(rm, __shfl_xor_sync(0xffffffffu, rm, 4));
            rm = fmaxf(rm, __shfl_xor_sync(0xffffffffu, rm, 8));
            float mn = fmaxf(m1, rm);
            float sc = __expf(m1 - mn);
            float p0 = __expf(S1[0] - mn), p1 = __expf(S1[1] - mn);
            float p2 = __expf(S1[2] - mn), p3 = __expf(S1[3] - mn);
            float rs = (p0 + p1) + (p2 + p3);
            rs += __shfl_xor_sync(0xffffffffu, rs, 1);
            rs += __shfl_xor_sync(0xffffffffu, rs, 2);
            rs += __shfl_xor_sync(0xffffffffu, rs, 4);
            rs += __shfl_xor_sync(0xffffffffu, rs, 8);
            l1 = l1 * sc + rs;
            m1 = mn;
            if (tc == 0) sSc[rA + 1] = sc;
            sP[(rA + 1) * 64 + tc     ] = p0;
            sP[(rA + 1) * 64 + tc + 16] = p1;
            sP[(rA + 1) * 64 + tc + 32] = p2;
            sP[(rA + 1) * 64 + tc + 48] = p3;
        }
        __syncthreads();

        // ---- load full V tile [64][512] ----
        const float* Vg = g_V + ((size_t)(b * cfg::NPIX + jt * cfg::BKV)) * 512;
#pragma unroll
        for (int rep = 0; rep < 32; rep++) {
            int s   = t + rep * 256;
            int row = s >> 7;
            int c4  = (s & 127) << 2;
            *(float4*)(sV + row * 512 + c4) = *(const float4*)(Vg + row * 512 + c4);
        }
        __syncthreads();

        // ---- rescale O, then O += P @ V (map B) ----
#pragma unroll
        for (int rr = 0; rr < 8; rr++) {
            float sc = sSc[rB + rr];
#pragma unroll
            for (int cc = 0; cc < 8; cc++) O[rr][cc] *= sc;
        }
#pragma unroll 2
        for (int j = 0; j < cfg::BKV; j++) {
            float4 v0 = *(const float4*)(sV + j * 512 + c0);
            float4 v1 = *(const float4*)(sV + j * 512 + c0 + 4);
#pragma unroll
            for (int rr = 0; rr < 8; rr++) {
                float p = sP[(rB + rr) * 64 + j];
                O[rr][0] += p * v0.x; O[rr][1] += p * v0.y;
                O[rr][2] += p * v0.z; O[rr][3] += p * v0.w;
                O[rr][4] += p * v1.x; O[rr][5] += p * v1.y;
                O[rr][6] += p * v1.z; O[rr][7] += p * v1.w;
            }
        }
    }

    // ---- finalize: divide by l, write out[b][c][i] (i contiguous) ----
    if (tc == 0) { sL[rA] = l0; sL[rA + 1] = l1; }
    __syncthreads();
    float inv[8];
#pragma unroll
    for (int rr = 0; rr < 8; rr++) inv[rr] = 1.f / sL[rB + rr];

#pragma unroll
    for (int cc = 0; cc < 8; cc++) {
        int c = c0 + cc;
        float4 y0 = make_float4(O[0][cc] * inv[0], O[1][cc] * inv[1],
                                O[2][cc] * inv[2], O[3][cc] * inv[3]);
        float4 y1 = make_float4(O[4][cc] * inv[4], O[5][cc] * inv[5],
                                O[6][cc] * inv[6], O[7][cc] * inv[7]);
        float* dst = out + ((size_t)(b * 512 + c)) * cfg::NPIX + it * cfg::BQ + rB;
        *(float4*)(dst)     = y0;
        *(float4*)(dst + 4) = y1;
    }
}

// ---------------------------------------------------------------------------
extern "C" void kernel_launch(void* const* d_in, const int* in_sizes, int n_in,
                              void* d_out, int out_size)
{
    const float* x   = (const float*)d_in[0];
    const float* f_w = (const float*)d_in[1];
    const float* f_b = (const float*)d_in[2];
    const float* g_w = (const float*)d_in[3];
    const float* g_b = (const float*)d_in[4];
    const float* h_w = (const float*)d_in[5];
    const float* h_b = (const float*)d_in[6];
    float* out = (float*)d_out;

    (void)in_sizes; (void)n_in; (void)out_size;

    cudaFuncSetAttribute(attn_kernel,
                         cudaFuncAttributeMaxDynamicSharedMemorySize,
                         cfg::SMEM_FLOATS * (int)sizeof(float));

    proj_kernel<<<dim3(32, 8, 4), 256>>>(x, f_w, f_b, g_w, g_b, h_w, h_b);
    attn_kernel<<<dim3(cfg::NPIX / cfg::BQ, 4), 256,
                  cfg::SMEM_FLOATS * sizeof(float)>>>(out);
}

// round 5
// speedup vs baseline: 3.2158x; 3.2158x over previous
#include <cuda_runtime.h>
#include <cuda_bf16.h>
#include <cstdint>

// ---------------------------------------------------------------------------
// SAGAN self-attention, B=4, C=512, H=W=64 (N=4096), fp32 in/out.
// Tensor-core pipeline via legacy mma.sync (tcgen05 PTX not accepted by the
// harness's compute_100 PTX stage). bf16 hi/lo 3-product split => ~fp32.
//   K1 proj (FFMA):  Q',K' = split(f,g proj) [b][n][hi256|lo256]
//                    V'    = split(h proj)   [b][c][hi4096|lo4096]
//   K2 gemm(0): E[b][i][j] = Q_i . K_j       (HMMA, fp32 accum)
//   K3 softmax: P = softmax_j(E) -> split    [b][i][hi4096|lo4096]
//   K4 gemm(1): out[b][c][i] = sum_j P[i][j] V[c][j]
// ---------------------------------------------------------------------------

#define BATCH 4
#define NPIX  4096
#define CIN   512
#define CV    512

__device__ __align__(16) __nv_bfloat16 g_Qs[(size_t)BATCH * NPIX * 512];
__device__ __align__(16) __nv_bfloat16 g_Ks[(size_t)BATCH * NPIX * 512];
__device__ __align__(16) __nv_bfloat16 g_Vs[(size_t)BATCH * CV   * 8192];
__device__ __align__(16) float         g_E [(size_t)BATCH * NPIX * NPIX];
__device__ __align__(16) __nv_bfloat16 g_P [(size_t)BATCH * NPIX * 8192];

#define SWZ128(x) ((x) ^ (((x) >> 3) & 0x70))

__device__ __forceinline__ uint32_t smem_u32(const void* p) {
    uint32_t a;
    asm("{ .reg .u64 t; cvta.to.shared.u64 t, %1; cvt.u32.u64 %0, t; }"
        : "=r"(a) : "l"(p));
    return a;
}
__device__ __forceinline__ void cp16(uint32_t saddr, const void* g) {
    asm volatile("cp.async.cg.shared.global [%0], [%1], 16;"
                 :: "r"(saddr), "l"(g));
}
#define CP_COMMIT() asm volatile("cp.async.commit_group;" ::: "memory")
#define CP_WAIT(n)  asm volatile("cp.async.wait_group %0;" :: "n"(n) : "memory")

__device__ __forceinline__ void ldm_x4(uint32_t* r, uint32_t addr) {
    asm volatile("ldmatrix.sync.aligned.m8n8.x4.shared.b16 {%0,%1,%2,%3}, [%4];"
                 : "=r"(r[0]), "=r"(r[1]), "=r"(r[2]), "=r"(r[3]) : "r"(addr));
}
__device__ __forceinline__ void mma16816(float* c, const uint32_t* a,
                                         const uint32_t* b) {
    asm volatile(
        "mma.sync.aligned.m16n8k16.row.col.f32.bf16.bf16.f32 "
        "{%0,%1,%2,%3}, {%4,%5,%6,%7}, {%8,%9}, {%0,%1,%2,%3};"
        : "+f"(c[0]), "+f"(c[1]), "+f"(c[2]), "+f"(c[3])
        : "r"(a[0]), "r"(a[1]), "r"(a[2]), "r"(a[3]), "r"(b[0]), "r"(b[1]));
}

// ---------------------------------------------------------------------------
// K1: projection (FFMA GEMM). Y[n][o] = sum_c W[o][c] x[b][c][n] + bias,
// o stacked [f|g|h]; epilogue writes bf16 hi/lo splits.
// ---------------------------------------------------------------------------
__global__ __launch_bounds__(256)
void proj_kernel(const float* __restrict__ x,
                 const float* __restrict__ f_w, const float* __restrict__ f_b,
                 const float* __restrict__ g_w, const float* __restrict__ g_b,
                 const float* __restrict__ h_w, const float* __restrict__ h_b)
{
    __shared__ float sW[16][128];
    __shared__ float sX[16][128];

    const int t     = threadIdx.x;
    const int nBase = blockIdx.x * 128;
    const int oBase = blockIdx.y * 128;
    const int b     = blockIdx.z;

    const float* Wsrc; const float* Bsrc; int orow0;
    if (oBase < 256)      { Wsrc = f_w; Bsrc = f_b; orow0 = oBase;       }
    else if (oBase < 512) { Wsrc = g_w; Bsrc = g_b; orow0 = oBase - 256; }
    else                  { Wsrc = h_w; Bsrc = h_b; orow0 = oBase - 512; }

    const int tc = t & 15;
    const int tr = t >> 4;
    const int o0 = tc * 8;
    const int n0 = tr * 8;

    float acc[8][8];
#pragma unroll
    for (int i = 0; i < 8; i++)
#pragma unroll
        for (int j = 0; j < 8; j++) acc[i][j] = 0.f;

    const int ow = t & 127;
    const int kq = (t >> 7) * 8;

    for (int k0 = 0; k0 < CIN; k0 += 16) {
        __syncthreads();
        const float* wp = Wsrc + (size_t)(orow0 + ow) * CIN + k0 + kq;
        float4 w0 = *(const float4*)(wp);
        float4 w1 = *(const float4*)(wp + 4);
        sW[kq + 0][ow] = w0.x; sW[kq + 1][ow] = w0.y;
        sW[kq + 2][ow] = w0.z; sW[kq + 3][ow] = w0.w;
        sW[kq + 4][ow] = w1.x; sW[kq + 5][ow] = w1.y;
        sW[kq + 6][ow] = w1.z; sW[kq + 7][ow] = w1.w;
#pragma unroll
        for (int rep = 0; rep < 2; rep++) {
            int s   = t + rep * 256;
            int row = s >> 5;
            int c4  = (s & 31) << 2;
            *(float4*)&sX[row][c4] =
                *(const float4*)(x + ((size_t)(b * CIN + k0 + row)) * NPIX + nBase + c4);
        }
        __syncthreads();
#pragma unroll
        for (int kk = 0; kk < 16; kk++) {
            float4 a0 = *(const float4*)&sW[kk][o0];
            float4 a1 = *(const float4*)&sW[kk][o0 + 4];
            float4 b0 = *(const float4*)&sX[kk][n0];
            float4 b1 = *(const float4*)&sX[kk][n0 + 4];
            float av[8] = {a0.x, a0.y, a0.z, a0.w, a1.x, a1.y, a1.z, a1.w};
            float bv[8] = {b0.x, b0.y, b0.z, b0.w, b1.x, b1.y, b1.z, b1.w};
#pragma unroll
            for (int nn = 0; nn < 8; nn++)
#pragma unroll
                for (int oo = 0; oo < 8; oo++)
                    acc[nn][oo] += bv[nn] * av[oo];
        }
    }

    float bias[8];
#pragma unroll
    for (int oo = 0; oo < 8; oo++) bias[oo] = Bsrc[orow0 + o0 + oo];

    if (oBase < 512) {
        __nv_bfloat16* dst = (oBase < 256) ? g_Qs : g_Ks;
        const int oc0 = orow0 + o0;
#pragma unroll
        for (int nn = 0; nn < 8; nn++) {
            const int n = nBase + n0 + nn;
            alignas(16) __nv_bfloat16 hv[8], lv[8];
#pragma unroll
            for (int oo = 0; oo < 8; oo++) {
                float vv = acc[nn][oo] + bias[oo];
                __nv_bfloat16 h = __float2bfloat16(vv);
                hv[oo] = h;
                lv[oo] = __float2bfloat16(vv - __bfloat162float(h));
            }
            size_t base = ((size_t)(b * NPIX + n)) * 512 + oc0;
            *(uint4*)(dst + base)       = *(const uint4*)hv;
            *(uint4*)(dst + base + 256) = *(const uint4*)lv;
        }
    } else {
#pragma unroll
        for (int oo = 0; oo < 8; oo++) {
            const int c = orow0 + o0 + oo;
            alignas(16) __nv_bfloat16 hv[8], lv[8];
#pragma unroll
            for (int nn = 0; nn < 8; nn++) {
                float vv = acc[nn][oo] + bias[oo];
                __nv_bfloat16 h = __float2bfloat16(vv);
                hv[nn] = h;
                lv[nn] = __float2bfloat16(vv - __bfloat162float(h));
            }
            size_t base = ((size_t)(b * CV + c)) * 8192 + nBase + n0;
            *(uint4*)(g_Vs + base)        = *(const uint4*)hv;
            *(uint4*)(g_Vs + base + NPIX) = *(const uint4*)lv;
        }
    }
}

// ---------------------------------------------------------------------------
// K2/K4: mma.sync bf16 GEMM. D[(nBase+n)*ldD + mBase+m] = sum_k A[m][k]B[n][k]
// CTA 128x128, K-step 64 (SW128 rows), 8 warps (2x4), warp tile 64x32.
// 3-product hi/lo split: stages (Ahi,Bhi),(Ahi,Blo),(Alo,Bhi) per k64 chunk.
// smem: A/B double buffer 4x16KB; epilogue reuses smem as C[128][132] fp32.
// ---------------------------------------------------------------------------
#define GEMM_SMEM 67584   // max(65536 pipeline, 128*132*4 epilogue)

__global__ void __launch_bounds__(256, 2)
gemm_bf16_kernel(float* __restrict__ Dout, int which)
{
    extern __shared__ __align__(1024) char smc[];
    const uint32_t smb = smem_u32(smc);

    const int t   = threadIdx.x;
    const int wid = t >> 5;
    const int lt  = t & 31;
    const int mBase = blockIdx.x * 128;
    const int nBase = blockIdx.y * 128;
    const int b     = blockIdx.z;

    const __nv_bfloat16* A; const __nv_bfloat16* B; float* D;
    int K, loOff, kchunks; size_t aB, bB, dB;
    if (which == 0) {
        A = g_Ks; B = g_Qs; D = g_E;
        K = 512;  loOff = 256;  kchunks = 4;
        aB = (size_t)NPIX * 512; bB = (size_t)NPIX * 512; dB = (size_t)NPIX * NPIX;
    } else {
        A = g_P;  B = g_Vs; D = Dout;
        K = 8192; loOff = 4096; kchunks = 64;
        aB = (size_t)NPIX * 8192; bB = (size_t)CV * 8192; dB = (size_t)CV * NPIX;
    }
    const __nv_bfloat16* Ab = A + (size_t)b * aB;
    const __nv_bfloat16* Bb = B + (size_t)b * bB;
    const int nStages = 3 * kchunks;

    // warp tiling
    const int m0 = (wid >> 2) * 64;
    const int n0 = (wid & 3) * 32;
    // ldmatrix per-thread row/byte selectors
    const int aRow  = (lt & 7) + ((lt >> 3) & 1) * 8;
    const int aByte = ((lt >> 4) & 1) * 16;
    const int bRow  = (lt & 7) + ((lt >> 4) & 1) * 8;
    const int bByte = ((lt >> 3) & 1) * 16;

    float acc[4][4][4];
#pragma unroll
    for (int i = 0; i < 4; i++)
#pragma unroll
        for (int j = 0; j < 4; j++)
#pragma unroll
            for (int r = 0; r < 4; r++) acc[i][j][r] = 0.f;

    // stage loader: 1024 uint4 for A + 1024 for B, 8 cp.async / thread
    auto load_stage = [&](int s, int buf) {
        const int cc   = s / 3;
        const int mode = s - cc * 3;
        const int kA = ((mode == 2) ? loOff : 0) + cc * 64;
        const int kB = ((mode == 1) ? loOff : 0) + cc * 64;
        const uint32_t offA = (uint32_t)buf * 32768u;
        const uint32_t offB = offA + 16384u;
#pragma unroll
        for (int i = 0; i < 4; i++) {
            int u = t + i * 256;
            int row = u >> 3, c16 = u & 7;
            cp16(smb + offA + SWZ128(row * 128 + c16 * 16),
                 Ab + (size_t)(mBase + row) * K + kA + c16 * 8);
        }
#pragma unroll
        for (int i = 0; i < 4; i++) {
            int u = t + i * 256;
            int row = u >> 3, c16 = u & 7;
            cp16(smb + offB + SWZ128(row * 128 + c16 * 16),
                 Bb + (size_t)(nBase + row) * K + kB + c16 * 8);
        }
        CP_COMMIT();
    };

    load_stage(0, 0);

    for (int s = 0; s < nStages; s++) {
        if (s + 1 < nStages) { load_stage(s + 1, (s + 1) & 1); CP_WAIT(1); }
        else                 { CP_WAIT(0); }
        __syncthreads();

        const uint32_t offA = (uint32_t)(s & 1) * 32768u;
        const uint32_t offB = offA + 16384u;
#pragma unroll
        for (int kq = 0; kq < 4; kq++) {
            const int kbyte = kq * 32;
            uint32_t af[4][4], bf2[2][4];
#pragma unroll
            for (int im = 0; im < 4; im++)
                ldm_x4(af[im], smb + offA +
                       SWZ128((m0 + im * 16 + aRow) * 128 + kbyte + aByte));
#pragma unroll
            for (int jp = 0; jp < 2; jp++)
                ldm_x4(bf2[jp], smb + offB +
                       SWZ128((n0 + jp * 16 + bRow) * 128 + kbyte + bByte));
#pragma unroll
            for (int im = 0; im < 4; im++)
#pragma unroll
                for (int jn = 0; jn < 4; jn++)
                    mma16816(acc[im][jn], af[im], &bf2[jn >> 1][(jn & 1) * 2]);
        }
        __syncthreads();
    }

    // -------- epilogue: transpose through smem, coalesced D writes --------
    float* sC = (float*)smc;   // [128 n][132 m]
    const int cr = lt >> 2;            // 0..7
    const int ccol = 2 * (lt & 3);     // 0,2,4,6
#pragma unroll
    for (int im = 0; im < 4; im++)
#pragma unroll
        for (int jn = 0; jn < 4; jn++) {
            const int m = m0 + im * 16 + cr;
            const int n = n0 + jn * 8 + ccol;
            sC[n * 132 + m]           = acc[im][jn][0];
            sC[(n + 1) * 132 + m]     = acc[im][jn][1];
            sC[n * 132 + m + 8]       = acc[im][jn][2];
            sC[(n + 1) * 132 + m + 8] = acc[im][jn][3];
        }
    __syncthreads();

    float* Db = D + (size_t)b * dB;
#pragma unroll
    for (int i = 0; i < 16; i++) {
        int idx = t + i * 256;          // float4 index over 128x128
        int n   = idx >> 5;
        int m4  = (idx & 31) << 2;
        float4 v = *(const float4*)(sC + n * 132 + m4);
        *(float4*)(Db + (size_t)(nBase + n) * NPIX + mBase + m4) = v;
    }
}

// ---------------------------------------------------------------------------
// K3: row softmax over E -> split P. One CTA per (b,i) row, 16 elems/thread.
// ---------------------------------------------------------------------------
__global__ __launch_bounds__(256)
void softmax_kernel()
{
    __shared__ float red[8];
    const int i = blockIdx.x, b = blockIdx.y, t = threadIdx.x;
    const float* row = g_E + ((size_t)(b * NPIX + i)) * NPIX;

    float4 v[4];
#pragma unroll
    for (int r = 0; r < 4; r++) v[r] = ((const float4*)row)[t + r * 256];

    float m = -1e30f;
#pragma unroll
    for (int r = 0; r < 4; r++)
        m = fmaxf(m, fmaxf(fmaxf(v[r].x, v[r].y), fmaxf(v[r].z, v[r].w)));
#pragma unroll
    for (int o = 16; o > 0; o >>= 1) m = fmaxf(m, __shfl_xor_sync(~0u, m, o));
    if ((t & 31) == 0) red[t >> 5] = m;
    __syncthreads();
    if (t < 8) {
        float x2 = red[t];
        x2 = fmaxf(x2, __shfl_xor_sync(0xffu, x2, 1));
        x2 = fmaxf(x2, __shfl_xor_sync(0xffu, x2, 2));
        x2 = fmaxf(x2, __shfl_xor_sync(0xffu, x2, 4));
        red[t] = x2;
    }
    __syncthreads();
    m = red[0];
    __syncthreads();

    float e[16];
    float ssum = 0.f;
#pragma unroll
    for (int r = 0; r < 4; r++) {
        e[r * 4 + 0] = __expf(v[r].x - m);
        e[r * 4 + 1] = __expf(v[r].y - m);
        e[r * 4 + 2] = __expf(v[r].z - m);
        e[r * 4 + 3] = __expf(v[r].w - m);
        ssum += (e[r*4+0] + e[r*4+1]) + (e[r*4+2] + e[r*4+3]);
    }
#pragma unroll
    for (int o = 16; o > 0; o >>= 1) ssum += __shfl_xor_sync(~0u, ssum, o);
    if ((t & 31) == 0) red[t >> 5] = ssum;
    __syncthreads();
    if (t < 8) {
        float x2 = red[t];
        x2 += __shfl_xor_sync(0xffu, x2, 1);
        x2 += __shfl_xor_sync(0xffu, x2, 2);
        x2 += __shfl_xor_sync(0xffu, x2, 4);
        red[t] = x2;
    }
    __syncthreads();
    const float inv = 1.f / red[0];

    const size_t pbase = ((size_t)(b * NPIX + i)) * 8192;
#pragma unroll
    for (int r = 0; r < 4; r++) {
        const int j0 = (t + r * 256) * 4;
        alignas(8) __nv_bfloat16 hv[4], lv[4];
#pragma unroll
        for (int k = 0; k < 4; k++) {
            float p = e[r * 4 + k] * inv;
            __nv_bfloat16 h = __float2bfloat16(p);
            hv[k] = h;
            lv[k] = __float2bfloat16(p - __bfloat162float(h));
        }
        *(uint2*)(g_P + pbase + j0)        = *(const uint2*)hv;
        *(uint2*)(g_P + pbase + NPIX + j0) = *(const uint2*)lv;
    }
}

// ---------------------------------------------------------------------------
extern "C" void kernel_launch(void* const* d_in, const int* in_sizes, int n_in,
                              void* d_out, int out_size)
{
    const float* x   = (const float*)d_in[0];
    const float* f_w = (const float*)d_in[1];
    const float* f_b = (const float*)d_in[2];
    const float* g_w = (const float*)d_in[3];
    const float* g_b = (const float*)d_in[4];
    const float* h_w = (const float*)d_in[5];
    const float* h_b = (const float*)d_in[6];
    float* out = (float*)d_out;
    (void)in_sizes; (void)n_in; (void)out_size;

    cudaFuncSetAttribute(gemm_bf16_kernel,
                         cudaFuncAttributeMaxDynamicSharedMemorySize, GEMM_SMEM);

    // K1: projections + hi/lo split
    proj_kernel<<<dim3(32, 8, 4), 256>>>(x, f_w, f_b, g_w, g_b, h_w, h_b);
    // K2: E[b][i][j] = Q.K^T  (m-tiles over j, n-tiles over i)
    gemm_bf16_kernel<<<dim3(32, 32, 4), 256, GEMM_SMEM>>>(nullptr, 0);
    // K3: P = softmax(E) + split
    softmax_kernel<<<dim3(NPIX, BATCH), 256>>>();
    // K4: out[b][c][i] = P.V^T (m-tiles over i, n-tiles over c)
    gemm_bf16_kernel<<<dim3(32, 4, 4), 256, GEMM_SMEM>>>(out, 1);
}

// round 6
// speedup vs baseline: 3.8710x; 1.2037x over previous
#include <cuda_runtime.h>
#include <cuda_bf16.h>
#include <cstdint>

// ---------------------------------------------------------------------------
// SAGAN self-attention, B=4, C=512, H=W=64 (N=4096), fp32 in/out.
// All GEMMs on tensor cores (mma.sync bf16, fp32 accum) with bf16 hi/lo
// 3-product splitting (drops only lo*lo => ~fp32 accuracy).
//   K0a wsplit:  W(f|g|h) -> g_Ws  [1024][hi512|lo512]
//   K0b xtrans:  x^T      -> g_Xts [b][n][hi512|lo512]
//   K1  proj  :  y = W.xT + bias -> split into g_Qs/g_Ks [b][n][hi|lo 256]
//                                   and g_Vs [b][c][hi4096|lo4096]
//   K2  gemm<0>: E[b][i][j] = Q_i . K_j
//   K3  softmax: P = softmax_j(E) -> split g_P [b][i][hi4096|lo4096]
//   K4  gemm<1>: out[b][c][i] = sum_j P[i][j] V[c][j]
// GEMM kernel: CTA 128m x 256n, k-step 64, 8 warps (warp tile 64x64),
// cp.async double buffer, SW128-swizzled smem, ldmatrix.x4 fragments.
// ---------------------------------------------------------------------------

#define BATCH 4
#define NPIX  4096
#define CIN   512
#define CV    512
#define SME   135168   // max(pipeline 96KB, epilogue 256*132*4)

__device__ __align__(16) __nv_bfloat16 g_Ws [(size_t)1024 * 1024];
__device__ __align__(16) __nv_bfloat16 g_Xts[(size_t)BATCH * NPIX * 1024];
__device__ __align__(16) __nv_bfloat16 g_Qs [(size_t)BATCH * NPIX * 512];
__device__ __align__(16) __nv_bfloat16 g_Ks [(size_t)BATCH * NPIX * 512];
__device__ __align__(16) __nv_bfloat16 g_Vs [(size_t)BATCH * CV   * 8192];
__device__ __align__(16) float         g_E  [(size_t)BATCH * NPIX * NPIX];
__device__ __align__(16) __nv_bfloat16 g_P  [(size_t)BATCH * NPIX * 8192];

#define SWZ128(x) ((x) ^ (((x) >> 3) & 0x70))

__device__ __forceinline__ uint32_t smem_u32(const void* p) {
    uint32_t a;
    asm("{ .reg .u64 t; cvta.to.shared.u64 t, %1; cvt.u32.u64 %0, t; }"
        : "=r"(a) : "l"(p));
    return a;
}
__device__ __forceinline__ void cp16(uint32_t saddr, const void* g) {
    asm volatile("cp.async.cg.shared.global [%0], [%1], 16;"
                 :: "r"(saddr), "l"(g));
}
#define CP_COMMIT() asm volatile("cp.async.commit_group;" ::: "memory")
#define CP_WAIT(n)  asm volatile("cp.async.wait_group %0;" :: "n"(n) : "memory")

__device__ __forceinline__ void ldm_x4(uint32_t* r, uint32_t addr) {
    asm volatile("ldmatrix.sync.aligned.m8n8.x4.shared.b16 {%0,%1,%2,%3}, [%4];"
                 : "=r"(r[0]), "=r"(r[1]), "=r"(r[2]), "=r"(r[3]) : "r"(addr));
}
__device__ __forceinline__ void mma16816(float* c, const uint32_t* a,
                                         const uint32_t* b) {
    asm volatile(
        "mma.sync.aligned.m16n8k16.row.col.f32.bf16.bf16.f32 "
        "{%0,%1,%2,%3}, {%4,%5,%6,%7}, {%8,%9}, {%0,%1,%2,%3};"
        : "+f"(c[0]), "+f"(c[1]), "+f"(c[2]), "+f"(c[3])
        : "r"(a[0]), "r"(a[1]), "r"(a[2]), "r"(a[3]), "r"(b[0]), "r"(b[1]));
}
__device__ __forceinline__ void split2(float v, __nv_bfloat16& h, __nv_bfloat16& l) {
    h = __float2bfloat16(v);
    l = __float2bfloat16(v - __bfloat162float(h));
}

// ---------------------------------------------------------------------------
// K0a: stack + split weights -> g_Ws[1024][hi512|lo512]
// ---------------------------------------------------------------------------
__global__ __launch_bounds__(512)
void wsplit_kernel(const float* __restrict__ f_w, const float* __restrict__ g_w,
                   const float* __restrict__ h_w)
{
    const int o = blockIdx.x;
    const int k = threadIdx.x;
    const float* src = (o < 256) ? f_w + (size_t)o * 512
                     : (o < 512) ? g_w + (size_t)(o - 256) * 512
                                 : h_w + (size_t)(o - 512) * 512;
    __nv_bfloat16 h, l;
    split2(src[k], h, l);
    g_Ws[(size_t)o * 1024 + k]       = h;
    g_Ws[(size_t)o * 1024 + 512 + k] = l;
}

// ---------------------------------------------------------------------------
// K0b: transpose + split x -> g_Xts[b][n][hi512|lo512]
// ---------------------------------------------------------------------------
__global__ __launch_bounds__(256)
void xtrans_kernel(const float* __restrict__ x)
{
    __shared__ float ts[32][33];
    const int tx = threadIdx.x, ty = threadIdx.y;
    const int n0 = blockIdx.x * 32, c0 = blockIdx.y * 32, b = blockIdx.z;
#pragma unroll
    for (int i = 0; i < 4; i++)
        ts[ty + i * 8][tx] =
            x[((size_t)(b * CIN + c0 + ty + i * 8)) * NPIX + n0 + tx];
    __syncthreads();
#pragma unroll
    for (int i = 0; i < 4; i++) {
        const int n = n0 + ty + i * 8;
        __nv_bfloat16 h, l;
        split2(ts[tx][ty + i * 8], h, l);
        size_t base = ((size_t)(b * NPIX + n)) * 1024 + c0 + tx;
        g_Xts[base]       = h;
        g_Xts[base + 512] = l;
    }
}

// ---------------------------------------------------------------------------
// Unified tensor-core GEMM.  D[m][n] = sum_k A[m][k] B[n][k] (both k-major,
// rows stored [hi K|lo K]). 3-product stages: (hi,hi),(Ahi,Blo),(Alo,Bhi).
// WHICH=0: A=g_Ks(j), B=g_Qs(i) -> g_E
// WHICH=1: A=g_P (i), B=g_Vs(c) -> out
// WHICH=2: A=g_Ws(o), B=g_Xts(n) -> split epilogue into g_Qs/g_Ks/g_Vs + bias
// ---------------------------------------------------------------------------
template <int WHICH>
__global__ void __launch_bounds__(256, 1)
gemm2_kernel(float* __restrict__ Dout,
             const float* __restrict__ fb, const float* __restrict__ gb,
             const float* __restrict__ hb)
{
    extern __shared__ __align__(1024) char smc[];
    const uint32_t smb = smem_u32(smc);

    const int t   = threadIdx.x;
    const int wid = t >> 5;
    const int lt  = t & 31;
    const int mBase = blockIdx.x * 128;
    const int nBase = blockIdx.y * 256;
    const int b     = blockIdx.z;

    const __nv_bfloat16* Ab; const __nv_bfloat16* Bb;
    int kchunks;
    if (WHICH == 0) {
        Ab = g_Ks + (size_t)b * NPIX * 512;
        Bb = g_Qs + (size_t)b * NPIX * 512;
        kchunks = 4;
    } else if (WHICH == 1) {
        Ab = g_P  + (size_t)b * NPIX * 8192;
        Bb = g_Vs + (size_t)b * CV   * 8192;
        kchunks = 64;
    } else {
        Ab = g_Ws;
        Bb = g_Xts + (size_t)b * NPIX * 1024;
        kchunks = 8;
    }
    const int loOff = kchunks * 64;
    const int K     = loOff * 2;       // row stride (hi|lo)
    const int nStages = 3 * kchunks;

    const int m0 = (wid >> 2) * 64;
    const int n0 = (wid & 3) * 64;
    const int aRow  = (lt & 7) + ((lt >> 3) & 1) * 8;
    const int aByte = ((lt >> 4) & 1) * 16;
    const int bRow  = (lt & 7) + ((lt >> 4) & 1) * 8;
    const int bByte = ((lt >> 3) & 1) * 16;

    float acc[4][8][4];
#pragma unroll
    for (int i = 0; i < 4; i++)
#pragma unroll
        for (int j = 0; j < 8; j++)
#pragma unroll
            for (int r = 0; r < 4; r++) acc[i][j][r] = 0.f;

    auto load_stage = [&](int cc, int mode, int buf) {
        const int kA = ((mode == 2) ? loOff : 0) + cc * 64;
        const int kB = ((mode == 1) ? loOff : 0) + cc * 64;
        const uint32_t offA = (uint32_t)buf * 49152u;
        const uint32_t offB = offA + 16384u;
#pragma unroll
        for (int i = 0; i < 4; i++) {
            int u = t + i * 256;
            int row = u >> 3, c16 = u & 7;
            cp16(smb + offA + SWZ128(row * 128 + c16 * 16),
                 Ab + (size_t)(mBase + row) * K + kA + c16 * 8);
        }
#pragma unroll
        for (int i = 0; i < 8; i++) {
            int u = t + i * 256;
            int row = u >> 3, c16 = u & 7;
            cp16(smb + offB + SWZ128(row * 128 + c16 * 16),
                 Bb + (size_t)(nBase + row) * K + kB + c16 * 8);
        }
        CP_COMMIT();
    };

    load_stage(0, 0, 0);
    int cc = 0, mode = 0;
    for (int s = 0; s < nStages; s++) {
        int ncc = cc, nmode = mode + 1;
        if (nmode == 3) { nmode = 0; ncc++; }
        if (s + 1 < nStages) { load_stage(ncc, nmode, (s + 1) & 1); CP_WAIT(1); }
        else                 { CP_WAIT(0); }
        __syncthreads();

        const uint32_t offA = (uint32_t)(s & 1) * 49152u;
        const uint32_t offB = offA + 16384u;
#pragma unroll
        for (int kq = 0; kq < 4; kq++) {
            const int kb = kq * 32;
            uint32_t af[4][4], bf[4][4];
#pragma unroll
            for (int im = 0; im < 4; im++)
                ldm_x4(af[im], smb + offA +
                       SWZ128((m0 + im * 16 + aRow) * 128 + kb + aByte));
#pragma unroll
            for (int jp = 0; jp < 4; jp++)
                ldm_x4(bf[jp], smb + offB +
                       SWZ128((n0 + jp * 16 + bRow) * 128 + kb + bByte));
#pragma unroll
            for (int im = 0; im < 4; im++)
#pragma unroll
                for (int jn = 0; jn < 8; jn++)
                    mma16816(acc[im][jn], af[im], &bf[jn >> 1][(jn & 1) * 2]);
        }
        __syncthreads();
        cc = ncc; mode = nmode;
    }

    const int cr   = lt >> 2;
    const int ccol = 2 * (lt & 3);

    if (WHICH <= 1) {
        // fp32 D, transposed through smem so m is the contiguous store dim
        float* sC = (float*)smc;   // [256 n][132 m]
#pragma unroll
        for (int im = 0; im < 4; im++)
#pragma unroll
            for (int jn = 0; jn < 8; jn++) {
                const int m = m0 + im * 16 + cr;
                const int n = n0 + jn * 8 + ccol;
                sC[n * 132 + m]           = acc[im][jn][0];
                sC[(n + 1) * 132 + m]     = acc[im][jn][1];
                sC[n * 132 + m + 8]       = acc[im][jn][2];
                sC[(n + 1) * 132 + m + 8] = acc[im][jn][3];
            }
        __syncthreads();
        float* Db = (WHICH == 0) ? g_E + (size_t)b * NPIX * NPIX
                                 : Dout + (size_t)b * CV * NPIX;
#pragma unroll
        for (int i = 0; i < 32; i++) {
            int idx = t + i * 256;
            int n = idx >> 5, m4 = (idx & 31) << 2;
            float4 v = *(const float4*)(sC + n * 132 + m4);
            *(float4*)(Db + (size_t)(nBase + n) * NPIX + mBase + m4) = v;
        }
    } else {
        // proj epilogue: +bias, split hi/lo, write Q/K ([n][o]) or V ([c][n])
        const float* bsel; int o0;
        if (mBase < 256)      { bsel = fb; o0 = mBase; }
        else if (mBase < 512) { bsel = gb; o0 = mBase - 256; }
        else                  { bsel = hb; o0 = mBase - 512; }

        if (mBase < 512) {
            float* sC = (float*)smc;   // [256 n][132 m]
#pragma unroll
            for (int im = 0; im < 4; im++) {
                const int m = m0 + im * 16 + cr;
                const float b0 = bsel[o0 + m], b1 = bsel[o0 + m + 8];
#pragma unroll
                for (int jn = 0; jn < 8; jn++) {
                    const int n = n0 + jn * 8 + ccol;
                    sC[n * 132 + m]           = acc[im][jn][0] + b0;
                    sC[(n + 1) * 132 + m]     = acc[im][jn][1] + b0;
                    sC[n * 132 + m + 8]       = acc[im][jn][2] + b1;
                    sC[(n + 1) * 132 + m + 8] = acc[im][jn][3] + b1;
                }
            }
            __syncthreads();
            __nv_bfloat16* dst = (mBase < 256) ? g_Qs : g_Ks;
            const int oc0 = mBase & 255;   // 0 or 128
#pragma unroll
            for (int i = 0; i < 16; i++) {
                int idx = t + i * 256;
                int n = idx >> 4, m8 = (idx & 15) << 3;
                alignas(16) __nv_bfloat16 hv[8], lv[8];
#pragma unroll
                for (int q = 0; q < 8; q++)
                    split2(sC[n * 132 + m8 + q], hv[q], lv[q]);
                size_t base = ((size_t)(b * NPIX + nBase + n)) * 512 + oc0 + m8;
                *(uint4*)(dst + base)       = *(const uint4*)hv;
                *(uint4*)(dst + base + 256) = *(const uint4*)lv;
            }
        } else {
            float* sC = (float*)smc;   // [128 m][260 n]
#pragma unroll
            for (int im = 0; im < 4; im++) {
                const int m = m0 + im * 16 + cr;
                const float b0 = bsel[o0 + m], b1 = bsel[o0 + m + 8];
#pragma unroll
                for (int jn = 0; jn < 8; jn++) {
                    const int n = n0 + jn * 8 + ccol;
                    sC[m * 260 + n]           = acc[im][jn][0] + b0;
                    sC[m * 260 + n + 1]       = acc[im][jn][1] + b0;
                    sC[(m + 8) * 260 + n]     = acc[im][jn][2] + b1;
                    sC[(m + 8) * 260 + n + 1] = acc[im][jn][3] + b1;
                }
            }
            __syncthreads();
#pragma unroll
            for (int i = 0; i < 32; i++) {
                int idx = t + i * 256;
                int m = idx >> 6, n4 = (idx & 63) << 2;
                alignas(8) __nv_bfloat16 hv[4], lv[4];
#pragma unroll
                for (int q = 0; q < 4; q++)
                    split2(sC[m * 260 + n4 + q], hv[q], lv[q]);
                size_t base = ((size_t)(b * CV + o0 + m)) * 8192 + nBase + n4;
                *(uint2*)(g_Vs + base)        = *(const uint2*)hv;
                *(uint2*)(g_Vs + base + 4096) = *(const uint2*)lv;
            }
        }
    }
}

// ---------------------------------------------------------------------------
// K3: row softmax over E -> split P. One CTA per (b,i) row, 16 elems/thread.
// ---------------------------------------------------------------------------
__global__ __launch_bounds__(256)
void softmax_kernel()
{
    __shared__ float red[8];
    const int i = blockIdx.x, b = blockIdx.y, t = threadIdx.x;
    const float* row = g_E + ((size_t)(b * NPIX + i)) * NPIX;

    float4 v[4];
#pragma unroll
    for (int r = 0; r < 4; r++) v[r] = ((const float4*)row)[t + r * 256];

    float m = -1e30f;
#pragma unroll
    for (int r = 0; r < 4; r++)
        m = fmaxf(m, fmaxf(fmaxf(v[r].x, v[r].y), fmaxf(v[r].z, v[r].w)));
#pragma unroll
    for (int o = 16; o > 0; o >>= 1) m = fmaxf(m, __shfl_xor_sync(~0u, m, o));
    if ((t & 31) == 0) red[t >> 5] = m;
    __syncthreads();
    if (t < 8) {
        float x2 = red[t];
        x2 = fmaxf(x2, __shfl_xor_sync(0xffu, x2, 1));
        x2 = fmaxf(x2, __shfl_xor_sync(0xffu, x2, 2));
        x2 = fmaxf(x2, __shfl_xor_sync(0xffu, x2, 4));
        red[t] = x2;
    }
    __syncthreads();
    m = red[0];
    __syncthreads();

    float e[16];
    float ssum = 0.f;
#pragma unroll
    for (int r = 0; r < 4; r++) {
        e[r * 4 + 0] = __expf(v[r].x - m);
        e[r * 4 + 1] = __expf(v[r].y - m);
        e[r * 4 + 2] = __expf(v[r].z - m);
        e[r * 4 + 3] = __expf(v[r].w - m);
        ssum += (e[r*4+0] + e[r*4+1]) + (e[r*4+2] + e[r*4+3]);
    }
#pragma unroll
    for (int o = 16; o > 0; o >>= 1) ssum += __shfl_xor_sync(~0u, ssum, o);
    if ((t & 31) == 0) red[t >> 5] = ssum;
    __syncthreads();
    if (t < 8) {
        float x2 = red[t];
        x2 += __shfl_xor_sync(0xffu, x2, 1);
        x2 += __shfl_xor_sync(0xffu, x2, 2);
        x2 += __shfl_xor_sync(0xffu, x2, 4);
        red[t] = x2;
    }
    __syncthreads();
    const float inv = 1.f / red[0];

    const size_t pbase = ((size_t)(b * NPIX + i)) * 8192;
#pragma unroll
    for (int r = 0; r < 4; r++) {
        const int j0 = (t + r * 256) * 4;
        alignas(8) __nv_bfloat16 hv[4], lv[4];
#pragma unroll
        for (int k = 0; k < 4; k++)
            split2(e[r * 4 + k] * inv, hv[k], lv[k]);
        *(uint2*)(g_P + pbase + j0)        = *(const uint2*)hv;
        *(uint2*)(g_P + pbase + NPIX + j0) = *(const uint2*)lv;
    }
}

// ---------------------------------------------------------------------------
extern "C" void kernel_launch(void* const* d_in, const int* in_sizes, int n_in,
                              void* d_out, int out_size)
{
    const float* x   = (const float*)d_in[0];
    const float* f_w = (const float*)d_in[1];
    const float* f_b = (const float*)d_in[2];
    const float* g_w = (const float*)d_in[3];
    const float* g_b = (const float*)d_in[4];
    const float* h_w = (const float*)d_in[5];
    const float* h_b = (const float*)d_in[6];
    float* out = (float*)d_out;
    (void)in_sizes; (void)n_in; (void)out_size;

    cudaFuncSetAttribute(gemm2_kernel<0>,
                         cudaFuncAttributeMaxDynamicSharedMemorySize, SME);
    cudaFuncSetAttribute(gemm2_kernel<1>,
                         cudaFuncAttributeMaxDynamicSharedMemorySize, SME);
    cudaFuncSetAttribute(gemm2_kernel<2>,
                         cudaFuncAttributeMaxDynamicSharedMemorySize, SME);

    // K0: weight split + x transpose/split
    wsplit_kernel<<<1024, 512>>>(f_w, g_w, h_w);
    xtrans_kernel<<<dim3(NPIX / 32, CIN / 32, BATCH), dim3(32, 8)>>>(x);
    // K1: projection GEMM (m = o:1024, n = pixels)
    gemm2_kernel<2><<<dim3(8, 16, 4), 256, SME>>>(nullptr, f_b, g_b, h_b);
    // K2: E[b][i][j] = Q.K^T (m = j, n = i)
    gemm2_kernel<0><<<dim3(32, 16, 4), 256, SME>>>(nullptr, f_b, g_b, h_b);
    // K3: P = softmax(E) + split
    softmax_kernel<<<dim3(NPIX, BATCH), 256>>>();
    // K4: out[b][c][i] = P.V^T (m = i, n = c)
    gemm2_kernel<1><<<dim3(32, 2, 4), 256, SME>>>(out, f_b, g_b, h_b);
}

// round 7
// speedup vs baseline: 3.9912x; 1.0310x over previous
#include <cuda_runtime.h>
#include <cuda_bf16.h>
#include <cstdint>

// ---------------------------------------------------------------------------
// SAGAN self-attention, B=4, C=512, H=W=64 (N=4096), fp32 in/out.
// All GEMMs on tensor cores (mma.sync bf16, fp32 accum) with bf16 hi/lo
// 3-product splitting (drops only lo*lo => ~fp32 accuracy).
// R7: chunk-granularity loading — per k64 chunk load {Ahi,Alo,Bhi,Blo} once
// (96KB, double buffered), 3 product passes from smem, 1 barrier pair/chunk.
//   K0a wsplit:  W(f|g|h) -> g_Ws  [1024][hi512|lo512]
//   K0b xtrans:  x^T      -> g_Xts [b][n][hi512|lo512]
//   K1  gemm<2>: proj + bias -> split g_Qs/g_Ks [b][n][hi|lo], g_Vs [b][c][hi|lo]
//   K2  gemm<0>: E[b][i][j] = Q_i . K_j
//   K3  softmax: P = softmax_j(E) -> split g_P [b][i][hi4096|lo4096]
//   K4  gemm<1>: out[b][c][i] = sum_j P[i][j] V[c][j]
// ---------------------------------------------------------------------------

#define BATCH 4
#define NPIX  4096
#define CIN   512
#define CV    512
#define SME   196608   // pipeline 2*96KB (epilogue needs 135168)

__device__ __align__(16) __nv_bfloat16 g_Ws [(size_t)1024 * 1024];
__device__ __align__(16) __nv_bfloat16 g_Xts[(size_t)BATCH * NPIX * 1024];
__device__ __align__(16) __nv_bfloat16 g_Qs [(size_t)BATCH * NPIX * 512];
__device__ __align__(16) __nv_bfloat16 g_Ks [(size_t)BATCH * NPIX * 512];
__device__ __align__(16) __nv_bfloat16 g_Vs [(size_t)BATCH * CV   * 8192];
__device__ __align__(16) float         g_E  [(size_t)BATCH * NPIX * NPIX];
__device__ __align__(16) __nv_bfloat16 g_P  [(size_t)BATCH * NPIX * 8192];

#define SWZ128(x) ((x) ^ (((x) >> 3) & 0x70))

__device__ __forceinline__ uint32_t smem_u32(const void* p) {
    uint32_t a;
    asm("{ .reg .u64 t; cvta.to.shared.u64 t, %1; cvt.u32.u64 %0, t; }"
        : "=r"(a) : "l"(p));
    return a;
}
__device__ __forceinline__ void cp16(uint32_t saddr, const void* g) {
    asm volatile("cp.async.cg.shared.global [%0], [%1], 16;"
                 :: "r"(saddr), "l"(g));
}
#define CP_COMMIT() asm volatile("cp.async.commit_group;" ::: "memory")
#define CP_WAIT(n)  asm volatile("cp.async.wait_group %0;" :: "n"(n) : "memory")

__device__ __forceinline__ void ldm_x4(uint32_t* r, uint32_t addr) {
    asm volatile("ldmatrix.sync.aligned.m8n8.x4.shared.b16 {%0,%1,%2,%3}, [%4];"
                 : "=r"(r[0]), "=r"(r[1]), "=r"(r[2]), "=r"(r[3]) : "r"(addr));
}
__device__ __forceinline__ void mma16816(float* c, const uint32_t* a,
                                         const uint32_t* b) {
    asm volatile(
        "mma.sync.aligned.m16n8k16.row.col.f32.bf16.bf16.f32 "
        "{%0,%1,%2,%3}, {%4,%5,%6,%7}, {%8,%9}, {%0,%1,%2,%3};"
        : "+f"(c[0]), "+f"(c[1]), "+f"(c[2]), "+f"(c[3])
        : "r"(a[0]), "r"(a[1]), "r"(a[2]), "r"(a[3]), "r"(b[0]), "r"(b[1]));
}
__device__ __forceinline__ void split2(float v, __nv_bfloat16& h, __nv_bfloat16& l) {
    h = __float2bfloat16(v);
    l = __float2bfloat16(v - __bfloat162float(h));
}

// ---------------------------------------------------------------------------
// K0a: stack + split weights -> g_Ws[1024][hi512|lo512]
// ---------------------------------------------------------------------------
__global__ __launch_bounds__(512)
void wsplit_kernel(const float* __restrict__ f_w, const float* __restrict__ g_w,
                   const float* __restrict__ h_w)
{
    const int o = blockIdx.x;
    const int k = threadIdx.x;
    const float* src = (o < 256) ? f_w + (size_t)o * 512
                     : (o < 512) ? g_w + (size_t)(o - 256) * 512
                                 : h_w + (size_t)(o - 512) * 512;
    __nv_bfloat16 h, l;
    split2(src[k], h, l);
    g_Ws[(size_t)o * 1024 + k]       = h;
    g_Ws[(size_t)o * 1024 + 512 + k] = l;
}

// ---------------------------------------------------------------------------
// K0b: transpose + split x -> g_Xts[b][n][hi512|lo512]
// ---------------------------------------------------------------------------
__global__ __launch_bounds__(256)
void xtrans_kernel(const float* __restrict__ x)
{
    __shared__ float ts[32][33];
    const int tx = threadIdx.x, ty = threadIdx.y;
    const int n0 = blockIdx.x * 32, c0 = blockIdx.y * 32, b = blockIdx.z;
#pragma unroll
    for (int i = 0; i < 4; i++)
        ts[ty + i * 8][tx] =
            x[((size_t)(b * CIN + c0 + ty + i * 8)) * NPIX + n0 + tx];
    __syncthreads();
#pragma unroll
    for (int i = 0; i < 4; i++) {
        const int n = n0 + ty + i * 8;
        __nv_bfloat16 h, l;
        split2(ts[tx][ty + i * 8], h, l);
        size_t base = ((size_t)(b * NPIX + n)) * 1024 + c0 + tx;
        g_Xts[base]       = h;
        g_Xts[base + 512] = l;
    }
}

// ---------------------------------------------------------------------------
// Unified tensor-core GEMM.  D[m][n] = sum_k A[m][k] B[n][k] (both k-major,
// rows stored [hi K|lo K]). Per chunk: load Ahi/Alo/Bhi/Blo once, compute
// AhiBhi + AhiBlo + AloBhi. CTA 128m x 256n, 8 warps (warp tile 64x64).
// WHICH=0: A=g_Ks(j), B=g_Qs(i) -> g_E
// WHICH=1: A=g_P (i), B=g_Vs(c) -> out
// WHICH=2: A=g_Ws(o), B=g_Xts(n) -> split epilogue into g_Qs/g_Ks/g_Vs + bias
// ---------------------------------------------------------------------------
template <int WHICH>
__global__ void __launch_bounds__(256, 1)
gemm2_kernel(float* __restrict__ Dout,
             const float* __restrict__ fb, const float* __restrict__ gb,
             const float* __restrict__ hb)
{
    extern __shared__ __align__(1024) char smc[];
    const uint32_t smb = smem_u32(smc);

    const int t   = threadIdx.x;
    const int wid = t >> 5;
    const int lt  = t & 31;
    const int mBase = blockIdx.x * 128;
    const int nBase = blockIdx.y * 256;
    const int b     = blockIdx.z;

    const __nv_bfloat16* Ab; const __nv_bfloat16* Bb;
    int kchunks;
    if (WHICH == 0) {
        Ab = g_Ks + (size_t)b * NPIX * 512;
        Bb = g_Qs + (size_t)b * NPIX * 512;
        kchunks = 4;
    } else if (WHICH == 1) {
        Ab = g_P  + (size_t)b * NPIX * 8192;
        Bb = g_Vs + (size_t)b * CV   * 8192;
        kchunks = 64;
    } else {
        Ab = g_Ws;
        Bb = g_Xts + (size_t)b * NPIX * 1024;
        kchunks = 8;
    }
    const int loOff = kchunks * 64;
    const int K     = loOff * 2;       // row stride (hi|lo)

    const int m0 = (wid >> 2) * 64;
    const int n0 = (wid & 3) * 64;
    const int aRow  = (lt & 7) + ((lt >> 3) & 1) * 8;
    const int aByte = ((lt >> 4) & 1) * 16;
    const int bRow  = (lt & 7) + ((lt >> 4) & 1) * 8;
    const int bByte = ((lt >> 3) & 1) * 16;

    float acc[4][8][4];
#pragma unroll
    for (int i = 0; i < 4; i++)
#pragma unroll
        for (int j = 0; j < 8; j++)
#pragma unroll
            for (int r = 0; r < 4; r++) acc[i][j][r] = 0.f;

    // per chunk: Ahi @ +0 (16K), Alo @ +16K, Bhi @ +32K (32K), Blo @ +64K
    auto load_chunk = [&](int cc, int buf) {
        const uint32_t base = (uint32_t)buf * 98304u;
        const int k0 = cc * 64;
#pragma unroll
        for (int i = 0; i < 4; i++) {
            int u = t + i * 256;
            int row = u >> 3, c16 = u & 7;
            uint32_t sw = SWZ128(row * 128 + c16 * 16);
            const __nv_bfloat16* gp = Ab + (size_t)(mBase + row) * K + k0 + c16 * 8;
            cp16(smb + base + sw, gp);
            cp16(smb + base + 16384u + sw, gp + loOff);
        }
#pragma unroll
        for (int i = 0; i < 8; i++) {
            int u = t + i * 256;
            int row = u >> 3, c16 = u & 7;
            uint32_t sw = SWZ128(row * 128 + c16 * 16);
            const __nv_bfloat16* gp = Bb + (size_t)(nBase + row) * K + k0 + c16 * 8;
            cp16(smb + base + 32768u + sw, gp);
            cp16(smb + base + 65536u + sw, gp + loOff);
        }
        CP_COMMIT();
    };

    load_chunk(0, 0);
    for (int cc = 0; cc < kchunks; cc++) {
        if (cc + 1 < kchunks) { load_chunk(cc + 1, (cc + 1) & 1); CP_WAIT(1); }
        else                  { CP_WAIT(0); }
        __syncthreads();

        const uint32_t ba   = (uint32_t)(cc & 1) * 98304u;
        const uint32_t oAhi = ba, oAlo = ba + 16384u;
        const uint32_t oBhi = ba + 32768u, oBlo = ba + 65536u;

        // pass A: Ahi * (Bhi, Blo) — af fragments shared
#pragma unroll
        for (int kq = 0; kq < 4; kq++) {
            const int kb = kq * 32;
            uint32_t af[4][4], bf[4][4];
#pragma unroll
            for (int im = 0; im < 4; im++)
                ldm_x4(af[im], smb + oAhi +
                       SWZ128((m0 + im * 16 + aRow) * 128 + kb + aByte));
#pragma unroll
            for (int jp = 0; jp < 4; jp++)
                ldm_x4(bf[jp], smb + oBhi +
                       SWZ128((n0 + jp * 16 + bRow) * 128 + kb + bByte));
#pragma unroll
            for (int im = 0; im < 4; im++)
#pragma unroll
                for (int jn = 0; jn < 8; jn++)
                    mma16816(acc[im][jn], af[im], &bf[jn >> 1][(jn & 1) * 2]);
#pragma unroll
            for (int jp = 0; jp < 4; jp++)
                ldm_x4(bf[jp], smb + oBlo +
                       SWZ128((n0 + jp * 16 + bRow) * 128 + kb + bByte));
#pragma unroll
            for (int im = 0; im < 4; im++)
#pragma unroll
                for (int jn = 0; jn < 8; jn++)
                    mma16816(acc[im][jn], af[im], &bf[jn >> 1][(jn & 1) * 2]);
        }
        // pass B: Alo * Bhi
#pragma unroll
        for (int kq = 0; kq < 4; kq++) {
            const int kb = kq * 32;
            uint32_t af[4][4], bf[4][4];
#pragma unroll
            for (int im = 0; im < 4; im++)
                ldm_x4(af[im], smb + oAlo +
                       SWZ128((m0 + im * 16 + aRow) * 128 + kb + aByte));
#pragma unroll
            for (int jp = 0; jp < 4; jp++)
                ldm_x4(bf[jp], smb + oBhi +
                       SWZ128((n0 + jp * 16 + bRow) * 128 + kb + bByte));
#pragma unroll
            for (int im = 0; im < 4; im++)
#pragma unroll
                for (int jn = 0; jn < 8; jn++)
                    mma16816(acc[im][jn], af[im], &bf[jn >> 1][(jn & 1) * 2]);
        }
        __syncthreads();
    }

    const int cr   = lt >> 2;
    const int ccol = 2 * (lt & 3);

    if (WHICH <= 1) {
        // fp32 D, transposed through smem so m is the contiguous store dim
        float* sC = (float*)smc;   // [256 n][132 m]
#pragma unroll
        for (int im = 0; im < 4; im++)
#pragma unroll
            for (int jn = 0; jn < 8; jn++) {
                const int m = m0 + im * 16 + cr;
                const int n = n0 + jn * 8 + ccol;
                sC[n * 132 + m]           = acc[im][jn][0];
                sC[(n + 1) * 132 + m]     = acc[im][jn][1];
                sC[n * 132 + m + 8]       = acc[im][jn][2];
                sC[(n + 1) * 132 + m + 8] = acc[im][jn][3];
            }
        __syncthreads();
        float* Db = (WHICH == 0) ? g_E + (size_t)b * NPIX * NPIX
                                 : Dout + (size_t)b * CV * NPIX;
#pragma unroll
        for (int i = 0; i < 32; i++) {
            int idx = t + i * 256;
            int n = idx >> 5, m4 = (idx & 31) << 2;
            float4 v = *(const float4*)(sC + n * 132 + m4);
            *(float4*)(Db + (size_t)(nBase + n) * NPIX + mBase + m4) = v;
        }
    } else {
        // proj epilogue: +bias, split hi/lo, write Q/K ([n][o]) or V ([c][n])
        const float* bsel; int o0;
        if (mBase < 256)      { bsel = fb; o0 = mBase; }
        else if (mBase < 512) { bsel = gb; o0 = mBase - 256; }
        else                  { bsel = hb; o0 = mBase - 512; }

        if (mBase < 512) {
            float* sC = (float*)smc;   // [256 n][132 m]
#pragma unroll
            for (int im = 0; im < 4; im++) {
                const int m = m0 + im * 16 + cr;
                const float b0 = bsel[o0 + m], b1 = bsel[o0 + m + 8];
#pragma unroll
                for (int jn = 0; jn < 8; jn++) {
                    const int n = n0 + jn * 8 + ccol;
                    sC[n * 132 + m]           = acc[im][jn][0] + b0;
                    sC[(n + 1) * 132 + m]     = acc[im][jn][1] + b0;
                    sC[n * 132 + m + 8]       = acc[im][jn][2] + b1;
                    sC[(n + 1) * 132 + m + 8] = acc[im][jn][3] + b1;
                }
            }
            __syncthreads();
            __nv_bfloat16* dst = (mBase < 256) ? g_Qs : g_Ks;
            const int oc0 = mBase & 255;   // 0 or 128
#pragma unroll
            for (int i = 0; i < 16; i++) {
                int idx = t + i * 256;
                int n = idx >> 4, m8 = (idx & 15) << 3;
                alignas(16) __nv_bfloat16 hv[8], lv[8];
#pragma unroll
                for (int q = 0; q < 8; q++)
                    split2(sC[n * 132 + m8 + q], hv[q], lv[q]);
                size_t base = ((size_t)(b * NPIX + nBase + n)) * 512 + oc0 + m8;
                *(uint4*)(dst + base)       = *(const uint4*)hv;
                *(uint4*)(dst + base + 256) = *(const uint4*)lv;
            }
        } else {
            float* sC = (float*)smc;   // [128 m][260 n]
#pragma unroll
            for (int im = 0; im < 4; im++) {
                const int m = m0 + im * 16 + cr;
                const float b0 = bsel[o0 + m], b1 = bsel[o0 + m + 8];
#pragma unroll
                for (int jn = 0; jn < 8; jn++) {
                    const int n = n0 + jn * 8 + ccol;
                    sC[m * 260 + n]           = acc[im][jn][0] + b0;
                    sC[m * 260 + n + 1]       = acc[im][jn][1] + b0;
                    sC[(m + 8) * 260 + n]     = acc[im][jn][2] + b1;
                    sC[(m + 8) * 260 + n + 1] = acc[im][jn][3] + b1;
                }
            }
            __syncthreads();
#pragma unroll
            for (int i = 0; i < 32; i++) {
                int idx = t + i * 256;
                int m = idx >> 6, n4 = (idx & 63) << 2;
                alignas(8) __nv_bfloat16 hv[4], lv[4];
#pragma unroll
                for (int q = 0; q < 4; q++)
                    split2(sC[m * 260 + n4 + q], hv[q], lv[q]);
                size_t base = ((size_t)(b * CV + o0 + m)) * 8192 + nBase + n4;
                *(uint2*)(g_Vs + base)        = *(const uint2*)hv;
                *(uint2*)(g_Vs + base + 4096) = *(const uint2*)lv;
            }
        }
    }
}

// ---------------------------------------------------------------------------
// K3: row softmax over E -> split P. One CTA per (b,i) row, 16 elems/thread.
// ---------------------------------------------------------------------------
__global__ __launch_bounds__(256)
void softmax_kernel()
{
    __shared__ float red[8];
    const int i = blockIdx.x, b = blockIdx.y, t = threadIdx.x;
    const float* row = g_E + ((size_t)(b * NPIX + i)) * NPIX;

    float4 v[4];
#pragma unroll
    for (int r = 0; r < 4; r++) v[r] = ((const float4*)row)[t + r * 256];

    float m = -1e30f;
#pragma unroll
    for (int r = 0; r < 4; r++)
        m = fmaxf(m, fmaxf(fmaxf(v[r].x, v[r].y), fmaxf(v[r].z, v[r].w)));
#pragma unroll
    for (int o = 16; o > 0; o >>= 1) m = fmaxf(m, __shfl_xor_sync(~0u, m, o));
    if ((t & 31) == 0) red[t >> 5] = m;
    __syncthreads();
    if (t < 8) {
        float x2 = red[t];
        x2 = fmaxf(x2, __shfl_xor_sync(0xffu, x2, 1));
        x2 = fmaxf(x2, __shfl_xor_sync(0xffu, x2, 2));
        x2 = fmaxf(x2, __shfl_xor_sync(0xffu, x2, 4));
        red[t] = x2;
    }
    __syncthreads();
    m = red[0];
    __syncthreads();

    float e[16];
    float ssum = 0.f;
#pragma unroll
    for (int r = 0; r < 4; r++) {
        e[r * 4 + 0] = __expf(v[r].x - m);
        e[r * 4 + 1] = __expf(v[r].y - m);
        e[r * 4 + 2] = __expf(v[r].z - m);
        e[r * 4 + 3] = __expf(v[r].w - m);
        ssum += (e[r*4+0] + e[r*4+1]) + (e[r*4+2] + e[r*4+3]);
    }
#pragma unroll
    for (int o = 16; o > 0; o >>= 1) ssum += __shfl_xor_sync(~0u, ssum, o);
    if ((t & 31) == 0) red[t >> 5] = ssum;
    __syncthreads();
    if (t < 8) {
        float x2 = red[t];
        x2 += __shfl_xor_sync(0xffu, x2, 1);
        x2 += __shfl_xor_sync(0xffu, x2, 2);
        x2 += __shfl_xor_sync(0xffu, x2, 4);
        red[t] = x2;
    }
    __syncthreads();
    const float inv = 1.f / red[0];

    const size_t pbase = ((size_t)(b * NPIX + i)) * 8192;
#pragma unroll
    for (int r = 0; r < 4; r++) {
        const int j0 = (t + r * 256) * 4;
        alignas(8) __nv_bfloat16 hv[4], lv[4];
#pragma unroll
        for (int k = 0; k < 4; k++)
            split2(e[r * 4 + k] * inv, hv[k], lv[k]);
        *(uint2*)(g_P + pbase + j0)        = *(const uint2*)hv;
        *(uint2*)(g_P + pbase + NPIX + j0) = *(const uint2*)lv;
    }
}

// ---------------------------------------------------------------------------
extern "C" void kernel_launch(void* const* d_in, const int* in_sizes, int n_in,
                              void* d_out, int out_size)
{
    const float* x   = (const float*)d_in[0];
    const float* f_w = (const float*)d_in[1];
    const float* f_b = (const float*)d_in[2];
    const float* g_w = (const float*)d_in[3];
    const float* g_b = (const float*)d_in[4];
    const float* h_w = (const float*)d_in[5];
    const float* h_b = (const float*)d_in[6];
    float* out = (float*)d_out;
    (void)in_sizes; (void)n_in; (void)out_size;

    cudaFuncSetAttribute(gemm2_kernel<0>,
                         cudaFuncAttributeMaxDynamicSharedMemorySize, SME);
    cudaFuncSetAttribute(gemm2_kernel<1>,
                         cudaFuncAttributeMaxDynamicSharedMemorySize, SME);
    cudaFuncSetAttribute(gemm2_kernel<2>,
                         cudaFuncAttributeMaxDynamicSharedMemorySize, SME);

    // K0: weight split + x transpose/split
    wsplit_kernel<<<1024, 512>>>(f_w, g_w, h_w);
    xtrans_kernel<<<dim3(NPIX / 32, CIN / 32, BATCH), dim3(32, 8)>>>(x);
    // K1: projection GEMM (m = o:1024, n = pixels)
    gemm2_kernel<2><<<dim3(8, 16, 4), 256, SME>>>(nullptr, f_b, g_b, h_b);
    // K2: E[b][i][j] = Q.K^T (m = j, n = i)
    gemm2_kernel<0><<<dim3(32, 16, 4), 256, SME>>>(nullptr, f_b, g_b, h_b);
    // K3: P = softmax(E) + split
    softmax_kernel<<<dim3(NPIX, BATCH), 256>>>();
    // K4: out[b][c][i] = P.V^T (m = i, n = c)
    gemm2_kernel<1><<<dim3(32, 2, 4), 256, SME>>>(out, f_b, g_b, h_b);
}

// round 8
// speedup vs baseline: 5.6635x; 1.4190x over previous
#include <cuda_runtime.h>
#include <cuda_bf16.h>
#include <cstdint>

// ---------------------------------------------------------------------------
// SAGAN self-attention, B=4, C=512, H=W=64 (N=4096), fp32 in/out.
// R8: all GEMMs via int8 tensor cores (mma.sync m16n8k32 s8.s8.s32).
// 16-bit fixed point per row: v = s*(256*d1 + d2), s = rowmax/32512.
// D = sA*sB*(65536*acc(d1e1) + 256*acc(d1e2+d2e1))   [d2e2 dropped, ~2^-14]
// Exact s32 accumulation; epilogue combines via int64 + double.
//   xtrans   : x^T -> g_Xtf fp32
//   qrows    : rowwise quantize (W rows, Xt rows, Q/K/V rows, ...)
//   gemm<2>  : proj (W x Xt) + bias -> g_Qf/g_Kf/g_Vf fp32
//   gemm<0>  : E = Q.K^T -> g_E fp32
//   softmax  : P = softmax(E) -> digits g_Pd + scale (exact: d = rint(e*32512))
//   gemm<1>  : out = P.V^T
// ---------------------------------------------------------------------------

#define BATCH 4
#define NPIX  4096
#define CIN   512
#define CV    512
#define SME   131072   // 2 x 64KB chunk buffers; epilogue reuses 67.6KB

// fp32 staging
__device__ __align__(16) float  g_Xtf[(size_t)BATCH * NPIX * 512];
__device__ __align__(16) float  g_Qf [(size_t)BATCH * NPIX * 256];
__device__ __align__(16) float  g_Kf [(size_t)BATCH * NPIX * 256];
__device__ __align__(16) float  g_Vf [(size_t)BATCH * CV   * 4096];
__device__ __align__(16) float  g_E  [(size_t)BATCH * NPIX * NPIX];
// digit buffers: rows stored [d1 K | d2 K]
__device__ __align__(16) int8_t g_Wd [(size_t)1024 * 1024];
__device__ __align__(16) int8_t g_Xtd[(size_t)BATCH * NPIX * 1024];
__device__ __align__(16) int8_t g_Qd [(size_t)BATCH * NPIX * 512];
__device__ __align__(16) int8_t g_Kd [(size_t)BATCH * NPIX * 512];
__device__ __align__(16) int8_t g_Vd [(size_t)BATCH * CV   * 8192];
__device__ __align__(16) int8_t g_Pd [(size_t)BATCH * NPIX * 8192];
// row scales
__device__ float g_Wsc [1024];
__device__ float g_Xsc [(size_t)BATCH * NPIX];
__device__ float g_Qsc [(size_t)BATCH * NPIX];
__device__ float g_Ksc [(size_t)BATCH * NPIX];
__device__ float g_Vsc [(size_t)BATCH * CV];
__device__ float g_Psc [(size_t)BATCH * NPIX];

#define SWZ128(x) ((x) ^ (((x) >> 3) & 0x70))

__device__ __forceinline__ uint32_t smem_u32(const void* p) {
    uint32_t a;
    asm("{ .reg .u64 t; cvta.to.shared.u64 t, %1; cvt.u32.u64 %0, t; }"
        : "=r"(a) : "l"(p));
    return a;
}
__device__ __forceinline__ void cp16(uint32_t saddr, const void* g) {
    asm volatile("cp.async.cg.shared.global [%0], [%1], 16;"
                 :: "r"(saddr), "l"(g));
}
#define CP_COMMIT() asm volatile("cp.async.commit_group;" ::: "memory")
#define CP_WAIT(n)  asm volatile("cp.async.wait_group %0;" :: "n"(n) : "memory")

__device__ __forceinline__ void ldm_x4(uint32_t* r, uint32_t addr) {
    asm volatile("ldmatrix.sync.aligned.m8n8.x4.shared.b16 {%0,%1,%2,%3}, [%4];"
                 : "=r"(r[0]), "=r"(r[1]), "=r"(r[2]), "=r"(r[3]) : "r"(addr));
}
__device__ __forceinline__ void mma_s8(int* c, const uint32_t* a,
                                       const uint32_t* b) {
    asm volatile(
        "mma.sync.aligned.m16n8k32.row.col.s32.s8.s8.s32 "
        "{%0,%1,%2,%3}, {%4,%5,%6,%7}, {%8,%9}, {%0,%1,%2,%3};"
        : "+r"(c[0]), "+r"(c[1]), "+r"(c[2]), "+r"(c[3])
        : "r"(a[0]), "r"(a[1]), "r"(a[2]), "r"(a[3]), "r"(b[0]), "r"(b[1]));
}
__device__ __forceinline__ double comb(int hi, int mid) {
    return (double)(((long long)hi << 16) + ((long long)mid << 8));
}

// ---------------------------------------------------------------------------
// transpose x -> g_Xtf [b][n][512] fp32
// ---------------------------------------------------------------------------
__global__ __launch_bounds__(256)
void xtrans_kernel(const float* __restrict__ x)
{
    __shared__ float ts[32][33];
    const int tx = threadIdx.x, ty = threadIdx.y;
    const int n0 = blockIdx.x * 32, c0 = blockIdx.y * 32, b = blockIdx.z;
#pragma unroll
    for (int i = 0; i < 4; i++)
        ts[ty + i * 8][tx] =
            x[((size_t)(b * CIN + c0 + ty + i * 8)) * NPIX + n0 + tx];
    __syncthreads();
#pragma unroll
    for (int i = 0; i < 4; i++) {
        const int n = n0 + ty + i * 8;
        g_Xtf[((size_t)(b * NPIX + n)) * 512 + c0 + tx] = ts[tx][ty + i * 8];
    }
}

// ---------------------------------------------------------------------------
// qrows: per-row 16-bit fixed-point quantization.
// src row [K] fp32 -> dst row [d1 K | d2 K] s8, sc[row] = rowmax/32512.
// ---------------------------------------------------------------------------
__global__ __launch_bounds__(256)
void qrows_kernel(const float* __restrict__ src, int8_t* __restrict__ dst,
                  float* __restrict__ sc, int K)
{
    __shared__ float red[8];
    const int r = blockIdx.x, t = threadIdx.x;
    const float* row = src + (size_t)r * K;

    float mx = 0.f;
    for (int k = t; k < K; k += 256) mx = fmaxf(mx, fabsf(row[k]));
#pragma unroll
    for (int o = 16; o > 0; o >>= 1) mx = fmaxf(mx, __shfl_xor_sync(~0u, mx, o));
    if ((t & 31) == 0) red[t >> 5] = mx;
    __syncthreads();
    if (t < 8) {
        float v = red[t];
        v = fmaxf(v, __shfl_xor_sync(0xffu, v, 1));
        v = fmaxf(v, __shfl_xor_sync(0xffu, v, 2));
        v = fmaxf(v, __shfl_xor_sync(0xffu, v, 4));
        red[t] = v;
    }
    __syncthreads();
    mx = red[0];
    const float q = (mx > 0.f) ? 32512.f / mx : 0.f;
    if (t == 0) sc[r] = mx * (1.f / 32512.f);

    int8_t* d1p = dst + (size_t)r * (2 * K);
    for (int k = t; k < K; k += 256) {
        int d  = __float2int_rn(row[k] * q);
        int d1 = (d + 128) >> 8;
        d1p[k]     = (int8_t)d1;
        d1p[K + k] = (int8_t)(d - (d1 << 8));
    }
}

// ---------------------------------------------------------------------------
// Unified int8 GEMM. D[m][n] = sum_k A[m][k] B[n][k], rows [d1 K|d2 K] s8.
// CTA 128m x 128n, k-chunk 128 (one SW128 row per digit tile), double buffer.
// 8 warps, warp tile 64x32. Two s32 accumulators: accA = d1e1 (w 65536),
// accB = d1e2 + d2e1 (w 256).
// WHICH=0: A=g_Kd(j), B=g_Qd(i) -> g_E fp32
// WHICH=1: A=g_Pd(i), B=g_Vd(c) -> out fp32
// WHICH=2: A=g_Wd(o), B=g_Xtd(n) -> +bias -> g_Qf/g_Kf ([b][n][o]), g_Vf ([b][c][n])
// ---------------------------------------------------------------------------
template <int WHICH>
__global__ void __launch_bounds__(256, 1)
gemm_s8_kernel(float* __restrict__ Dout,
               const float* __restrict__ fb, const float* __restrict__ gb,
               const float* __restrict__ hb)
{
    extern __shared__ __align__(1024) char smc[];
    const uint32_t smb = smem_u32(smc);

    const int t   = threadIdx.x;
    const int wid = t >> 5;
    const int lt  = t & 31;
    const int mBase = blockIdx.x * 128;
    const int nBase = blockIdx.y * 128;
    const int b     = blockIdx.z;

    const int8_t* Ab; const int8_t* Bb;
    const float* sAv; const float* sBv;
    int kchunks;
    if (WHICH == 0) {
        Ab = g_Kd + (size_t)b * NPIX * 512;
        Bb = g_Qd + (size_t)b * NPIX * 512;
        sAv = g_Ksc + (size_t)b * NPIX;
        sBv = g_Qsc + (size_t)b * NPIX;
        kchunks = 2;
    } else if (WHICH == 1) {
        Ab = g_Pd + (size_t)b * NPIX * 8192;
        Bb = g_Vd + (size_t)b * CV * 8192;
        sAv = g_Psc + (size_t)b * NPIX;
        sBv = g_Vsc + (size_t)b * CV;
        kchunks = 32;
    } else {
        Ab = g_Wd;
        Bb = g_Xtd + (size_t)b * NPIX * 1024;
        sAv = g_Wsc;
        sBv = g_Xsc + (size_t)b * NPIX;
        kchunks = 4;
    }
    const int Koff    = kchunks * 128;   // digit-2 offset within a row
    const int strideA = Koff * 2;        // bytes per row

    const int m0 = (wid >> 2) * 64;
    const int n0 = (wid & 3) * 32;
    const int aRow  = (lt & 7) + ((lt >> 3) & 1) * 8;
    const int aByte = ((lt >> 4) & 1) * 16;
    const int bRow  = (lt & 7) + ((lt >> 4) & 1) * 8;
    const int bByte = ((lt >> 3) & 1) * 16;

    int accA[4][4][4], accB[4][4][4];
#pragma unroll
    for (int i = 0; i < 4; i++)
#pragma unroll
        for (int j = 0; j < 4; j++)
#pragma unroll
            for (int r = 0; r < 4; r++) { accA[i][j][r] = 0; accB[i][j][r] = 0; }

    // chunk buffer: A1 @0, A2 @16K, B1 @32K, B2 @48K (16KB tiles, 128x128 s8)
    auto load_chunk = [&](int cc, int buf) {
        const uint32_t base = (uint32_t)buf * 65536u;
        const int k0 = cc * 128;
#pragma unroll
        for (int i = 0; i < 4; i++) {
            int u = t + i * 256;
            int row = u >> 3, c16 = u & 7;
            uint32_t sw = SWZ128(row * 128 + c16 * 16);
            const int8_t* gp = Ab + (size_t)(mBase + row) * strideA + k0 + c16 * 16;
            cp16(smb + base + sw, gp);
            cp16(smb + base + 16384u + sw, gp + Koff);
        }
#pragma unroll
        for (int i = 0; i < 4; i++) {
            int u = t + i * 256;
            int row = u >> 3, c16 = u & 7;
            uint32_t sw = SWZ128(row * 128 + c16 * 16);
            const int8_t* gp = Bb + (size_t)(nBase + row) * strideA + k0 + c16 * 16;
            cp16(smb + base + 32768u + sw, gp);
            cp16(smb + base + 49152u + sw, gp + Koff);
        }
        CP_COMMIT();
    };

    load_chunk(0, 0);
    for (int cc = 0; cc < kchunks; cc++) {
        if (cc + 1 < kchunks) { load_chunk(cc + 1, (cc + 1) & 1); CP_WAIT(1); }
        else                  { CP_WAIT(0); }
        __syncthreads();

        const uint32_t ba  = (uint32_t)(cc & 1) * 65536u;
        const uint32_t oA1 = ba, oA2 = ba + 16384u;
        const uint32_t oB1 = ba + 32768u, oB2 = ba + 49152u;

#pragma unroll
        for (int kq = 0; kq < 4; kq++) {
            const int kb = kq * 32;                // 32 bytes = k32 step
            uint32_t a1[4][4], a2[4][4], b1[2][4], b2[2][4];
#pragma unroll
            for (int im = 0; im < 4; im++) {
                uint32_t sw = SWZ128((m0 + im * 16 + aRow) * 128 + kb + aByte);
                ldm_x4(a1[im], smb + oA1 + sw);
                ldm_x4(a2[im], smb + oA2 + sw);
            }
#pragma unroll
            for (int jp = 0; jp < 2; jp++) {
                uint32_t sw = SWZ128((n0 + jp * 16 + bRow) * 128 + kb + bByte);
                ldm_x4(b1[jp], smb + oB1 + sw);
                ldm_x4(b2[jp], smb + oB2 + sw);
            }
#pragma unroll
            for (int im = 0; im < 4; im++)
#pragma unroll
                for (int jn = 0; jn < 4; jn++) {
                    const uint32_t* e1 = &b1[jn >> 1][(jn & 1) * 2];
                    const uint32_t* e2 = &b2[jn >> 1][(jn & 1) * 2];
                    mma_s8(accA[im][jn], a1[im], e1);
                    mma_s8(accB[im][jn], a1[im], e2);
                    mma_s8(accB[im][jn], a2[im], e1);
                }
        }
        __syncthreads();
    }

    const int cr   = lt >> 2;
    const int ccol = 2 * (lt & 3);

    if (WHICH <= 1) {
        float* sC = (float*)smc;   // [128 n][132 m]
#pragma unroll
        for (int im = 0; im < 4; im++) {
            const int m = m0 + im * 16 + cr;
            const float sa0 = sAv[mBase + m], sa1 = sAv[mBase + m + 8];
#pragma unroll
            for (int jn = 0; jn < 4; jn++) {
                const int n = n0 + jn * 8 + ccol;
                const float sb0 = sBv[nBase + n], sb1 = sBv[nBase + n + 1];
                sC[n * 132 + m] =
                    (float)(comb(accA[im][jn][0], accB[im][jn][0]) * (double)(sa0 * sb0));
                sC[(n + 1) * 132 + m] =
                    (float)(comb(accA[im][jn][1], accB[im][jn][1]) * (double)(sa0 * sb1));
                sC[n * 132 + m + 8] =
                    (float)(comb(accA[im][jn][2], accB[im][jn][2]) * (double)(sa1 * sb0));
                sC[(n + 1) * 132 + m + 8] =
                    (float)(comb(accA[im][jn][3], accB[im][jn][3]) * (double)(sa1 * sb1));
            }
        }
        __syncthreads();
        float* Db = (WHICH == 0) ? g_E + (size_t)b * NPIX * NPIX
                                 : Dout + (size_t)b * CV * NPIX;
#pragma unroll
        for (int i = 0; i < 16; i++) {
            int idx = t + i * 256;
            int n = idx >> 5, m4 = (idx & 31) << 2;
            float4 v = *(const float4*)(sC + n * 132 + m4);
            *(float4*)(Db + (size_t)(nBase + n) * NPIX + mBase + m4) = v;
        }
    } else {
        const float* bsel; int o0;
        if (mBase < 256)      { bsel = fb; o0 = mBase; }
        else if (mBase < 512) { bsel = gb; o0 = mBase - 256; }
        else                  { bsel = hb; o0 = mBase - 512; }

        if (mBase < 512) {
            float* sC = (float*)smc;   // [128 n][132 m]
#pragma unroll
            for (int im = 0; im < 4; im++) {
                const int m = m0 + im * 16 + cr;
                const float sa0 = sAv[mBase + m], sa1 = sAv[mBase + m + 8];
                const float bi0 = bsel[o0 + m], bi1 = bsel[o0 + m + 8];
#pragma unroll
                for (int jn = 0; jn < 4; jn++) {
                    const int n = n0 + jn * 8 + ccol;
                    const float sb0 = sBv[nBase + n], sb1 = sBv[nBase + n + 1];
                    sC[n * 132 + m] =
                        (float)(comb(accA[im][jn][0], accB[im][jn][0]) * (double)(sa0 * sb0)) + bi0;
                    sC[(n + 1) * 132 + m] =
                        (float)(comb(accA[im][jn][1], accB[im][jn][1]) * (double)(sa0 * sb1)) + bi0;
                    sC[n * 132 + m + 8] =
                        (float)(comb(accA[im][jn][2], accB[im][jn][2]) * (double)(sa1 * sb0)) + bi1;
                    sC[(n + 1) * 132 + m + 8] =
                        (float)(comb(accA[im][jn][3], accB[im][jn][3]) * (double)(sa1 * sb1)) + bi1;
                }
            }
            __syncthreads();
            float* dst = (mBase < 256) ? g_Qf : g_Kf;
            const int oc0 = mBase & 255;   // 0 or 128
#pragma unroll
            for (int i = 0; i < 16; i++) {
                int idx = t + i * 256;
                int n = idx >> 5, m4 = (idx & 31) << 2;
                float4 v = *(const float4*)(sC + n * 132 + m4);
                *(float4*)(dst + ((size_t)(b * NPIX + nBase + n)) * 256 + oc0 + m4) = v;
            }
        } else {
            float* sC = (float*)smc;   // [128 m][132 n]
#pragma unroll
            for (int im = 0; im < 4; im++) {
                const int m = m0 + im * 16 + cr;
                const float sa0 = sAv[mBase + m], sa1 = sAv[mBase + m + 8];
                const float bi0 = bsel[o0 + m], bi1 = bsel[o0 + m + 8];
#pragma unroll
                for (int jn = 0; jn < 4; jn++) {
                    const int n = n0 + jn * 8 + ccol;
                    const float sb0 = sBv[nBase + n], sb1 = sBv[nBase + n + 1];
                    sC[m * 132 + n] =
                        (float)(comb(accA[im][jn][0], accB[im][jn][0]) * (double)(sa0 * sb0)) + bi0;
                    sC[m * 132 + n + 1] =
                        (float)(comb(accA[im][jn][1], accB[im][jn][1]) * (double)(sa0 * sb1)) + bi0;
                    sC[(m + 8) * 132 + n] =
                        (float)(comb(accA[im][jn][2], accB[im][jn][2]) * (double)(sa1 * sb0)) + bi1;
                    sC[(m + 8) * 132 + n + 1] =
                        (float)(comb(accA[im][jn][3], accB[im][jn][3]) * (double)(sa1 * sb1)) + bi1;
                }
            }
            __syncthreads();
#pragma unroll
            for (int i = 0; i < 16; i++) {
                int idx = t + i * 256;
                int m = idx >> 5, n4 = (idx & 31) << 2;
                float4 v = *(const float4*)(sC + m * 132 + n4);
                *(float4*)(g_Vf + ((size_t)(b * CV + o0 + m)) * 4096 + nBase + n4) = v;
            }
        }
    }
}

// ---------------------------------------------------------------------------
// softmax: row softmax over E -> P digits (exact: d = rint(e * 32512),
// since Pmax = inv => P/s = e*32512). scale = inv/32512.
// ---------------------------------------------------------------------------
__global__ __launch_bounds__(256)
void softmax_kernel()
{
    __shared__ float red[8];
    const int i = blockIdx.x, b = blockIdx.y, t = threadIdx.x;
    const float* row = g_E + ((size_t)(b * NPIX + i)) * NPIX;

    float4 v[4];
#pragma unroll
    for (int r = 0; r < 4; r++) v[r] = ((const float4*)row)[t + r * 256];

    float m = -1e30f;
#pragma unroll
    for (int r = 0; r < 4; r++)
        m = fmaxf(m, fmaxf(fmaxf(v[r].x, v[r].y), fmaxf(v[r].z, v[r].w)));
#pragma unroll
    for (int o = 16; o > 0; o >>= 1) m = fmaxf(m, __shfl_xor_sync(~0u, m, o));
    if ((t & 31) == 0) red[t >> 5] = m;
    __syncthreads();
    if (t < 8) {
        float x2 = red[t];
        x2 = fmaxf(x2, __shfl_xor_sync(0xffu, x2, 1));
        x2 = fmaxf(x2, __shfl_xor_sync(0xffu, x2, 2));
        x2 = fmaxf(x2, __shfl_xor_sync(0xffu, x2, 4));
        red[t] = x2;
    }
    __syncthreads();
    m = red[0];
    __syncthreads();

    float e[16];
    float ssum = 0.f;
#pragma unroll
    for (int r = 0; r < 4; r++) {
        e[r * 4 + 0] = __expf(v[r].x - m);
        e[r * 4 + 1] = __expf(v[r].y - m);
        e[r * 4 + 2] = __expf(v[r].z - m);
        e[r * 4 + 3] = __expf(v[r].w - m);
        ssum += (e[r*4+0] + e[r*4+1]) + (e[r*4+2] + e[r*4+3]);
    }
#pragma unroll
    for (int o = 16; o > 0; o >>= 1) ssum += __shfl_xor_sync(~0u, ssum, o);
    if ((t & 31) == 0) red[t >> 5] = ssum;
    __syncthreads();
    if (t < 8) {
        float x2 = red[t];
        x2 += __shfl_xor_sync(0xffu, x2, 1);
        x2 += __shfl_xor_sync(0xffu, x2, 2);
        x2 += __shfl_xor_sync(0xffu, x2, 4);
        red[t] = x2;
    }
    __syncthreads();
    const float inv = 1.f / red[0];
    if (t == 0) g_Psc[(size_t)b * NPIX + i] = inv * (1.f / 32512.f);

    int8_t* pb = g_Pd + ((size_t)(b * NPIX + i)) * 8192;
#pragma unroll
    for (int r = 0; r < 4; r++) {
        const int j0 = (t + r * 256) * 4;
        char d1v[4], d2v[4];
#pragma unroll
        for (int k = 0; k < 4; k++) {
            int d  = __float2int_rn(e[r * 4 + k] * 32512.f);
            int d1 = (d + 128) >> 8;
            d1v[k] = (char)d1;
            d2v[k] = (char)(d - (d1 << 8));
        }
        *(char4*)(pb + j0)        = make_char4(d1v[0], d1v[1], d1v[2], d1v[3]);
        *(char4*)(pb + 4096 + j0) = make_char4(d2v[0], d2v[1], d2v[2], d2v[3]);
    }
}

// ---------------------------------------------------------------------------
extern "C" void kernel_launch(void* const* d_in, const int* in_sizes, int n_in,
                              void* d_out, int out_size)
{
    const float* x   = (const float*)d_in[0];
    const float* f_w = (const float*)d_in[1];
    const float* f_b = (const float*)d_in[2];
    const float* g_w = (const float*)d_in[3];
    const float* g_b = (const float*)d_in[4];
    const float* h_w = (const float*)d_in[5];
    const float* h_b = (const float*)d_in[6];
    float* out = (float*)d_out;
    (void)in_sizes; (void)n_in; (void)out_size;

    cudaFuncSetAttribute(gemm_s8_kernel<0>,
                         cudaFuncAttributeMaxDynamicSharedMemorySize, SME);
    cudaFuncSetAttribute(gemm_s8_kernel<1>,
                         cudaFuncAttributeMaxDynamicSharedMemorySize, SME);
    cudaFuncSetAttribute(gemm_s8_kernel<2>,
                         cudaFuncAttributeMaxDynamicSharedMemorySize, SME);

    int8_t* wd; float* wsc; float* xtf; int8_t* xtd; float* xsc;
    cudaGetSymbolAddress((void**)&wd,  g_Wd);
    cudaGetSymbolAddress((void**)&wsc, g_Wsc);
    cudaGetSymbolAddress((void**)&xtf, g_Xtf);
    cudaGetSymbolAddress((void**)&xtd, g_Xtd);
    cudaGetSymbolAddress((void**)&xsc, g_Xsc);
    float* qf; float* kf; float* vf;
    int8_t* qd; int8_t* kd; int8_t* vd;
    float* qsc; float* ksc; float* vsc;
    cudaGetSymbolAddress((void**)&qf, g_Qf);  cudaGetSymbolAddress((void**)&kf, g_Kf);
    cudaGetSymbolAddress((void**)&vf, g_Vf);
    cudaGetSymbolAddress((void**)&qd, g_Qd);  cudaGetSymbolAddress((void**)&kd, g_Kd);
    cudaGetSymbolAddress((void**)&vd, g_Vd);
    cudaGetSymbolAddress((void**)&qsc, g_Qsc); cudaGetSymbolAddress((void**)&ksc, g_Ksc);
    cudaGetSymbolAddress((void**)&vsc, g_Vsc);

    // quantize weights (rows contiguous per matrix; o stacked [f|g|h])
    qrows_kernel<<<256, 256>>>(f_w, wd,                 wsc,       512);
    qrows_kernel<<<256, 256>>>(g_w, wd + 256 * 1024,    wsc + 256, 512);
    qrows_kernel<<<512, 256>>>(h_w, wd + 512 * 1024,    wsc + 512, 512);
    // x^T then quantize pixel rows
    xtrans_kernel<<<dim3(NPIX / 32, CIN / 32, BATCH), dim3(32, 8)>>>(x);
    qrows_kernel<<<BATCH * NPIX, 256>>>(xtf, xtd, xsc, 512);
    // proj GEMM -> fp32 Q/K/V
    gemm_s8_kernel<2><<<dim3(8, 32, 4), 256, SME>>>(nullptr, f_b, g_b, h_b);
    // quantize Q/K/V rows
    qrows_kernel<<<BATCH * NPIX, 256>>>(qf, qd, qsc, 256);
    qrows_kernel<<<BATCH * NPIX, 256>>>(kf, kd, ksc, 256);
    qrows_kernel<<<BATCH * CV,   256>>>(vf, vd, vsc, 4096);
    // E = Q.K^T
    gemm_s8_kernel<0><<<dim3(32, 32, 4), 256, SME>>>(nullptr, f_b, g_b, h_b);
    // softmax -> P digits
    softmax_kernel<<<dim3(NPIX, BATCH), 256>>>();
    // out = P.V^T
    gemm_s8_kernel<1><<<dim3(32, 4, 4), 256, SME>>>(out, f_b, g_b, h_b);
}

// round 9
// speedup vs baseline: 6.9452x; 1.2263x over previous
#include <cuda_runtime.h>
#include <cuda_bf16.h>
#include <cstdint>

// ---------------------------------------------------------------------------
// SAGAN self-attention, B=4, C=512, H=W=64 (N=4096), fp32 in/out.
// R9: int8 tensor-core pipeline (mma.sync m16n8k32 s8.s8.s32), 16-bit
// fixed-point rowwise quantization v = s*(256*d1 + d2), 3-product scheme
// (d2e2 dropped). GEMMs now CTA 128m x 64n, warp tile 32x32, occupancy 2
// (2 CTAs/SM), fp32 epilogue combine.
//   xtrans   : x^T -> g_Xtf fp32
//   qrows    : rowwise quantize -> digits + scale
//   gemm<2>  : proj (W x Xt) + bias -> g_Qf/g_Kf/g_Vf fp32
//   gemm<0>  : E = Q.K^T -> g_E fp32
//   softmax  : P = softmax(E) -> digits g_Pd + scale
//   gemm<1>  : out = P.V^T
// ---------------------------------------------------------------------------

#define BATCH 4
#define NPIX  4096
#define CIN   512
#define CV    512
#define SME   98304    // 2 x 48KB chunk buffers; epilogue reuses < 35KB

// fp32 staging
__device__ __align__(16) float  g_Xtf[(size_t)BATCH * NPIX * 512];
__device__ __align__(16) float  g_Qf [(size_t)BATCH * NPIX * 256];
__device__ __align__(16) float  g_Kf [(size_t)BATCH * NPIX * 256];
__device__ __align__(16) float  g_Vf [(size_t)BATCH * CV   * 4096];
__device__ __align__(16) float  g_E  [(size_t)BATCH * NPIX * NPIX];
// digit buffers: rows stored [d1 K | d2 K]
__device__ __align__(16) int8_t g_Wd [(size_t)1024 * 1024];
__device__ __align__(16) int8_t g_Xtd[(size_t)BATCH * NPIX * 1024];
__device__ __align__(16) int8_t g_Qd [(size_t)BATCH * NPIX * 512];
__device__ __align__(16) int8_t g_Kd [(size_t)BATCH * NPIX * 512];
__device__ __align__(16) int8_t g_Vd [(size_t)BATCH * CV   * 8192];
__device__ __align__(16) int8_t g_Pd [(size_t)BATCH * NPIX * 8192];
// row scales
__device__ float g_Wsc [1024];
__device__ float g_Xsc [(size_t)BATCH * NPIX];
__device__ float g_Qsc [(size_t)BATCH * NPIX];
__device__ float g_Ksc [(size_t)BATCH * NPIX];
__device__ float g_Vsc [(size_t)BATCH * CV];
__device__ float g_Psc [(size_t)BATCH * NPIX];

#define SWZ128(x) ((x) ^ (((x) >> 3) & 0x70))

__device__ __forceinline__ uint32_t smem_u32(const void* p) {
    uint32_t a;
    asm("{ .reg .u64 t; cvta.to.shared.u64 t, %1; cvt.u32.u64 %0, t; }"
        : "=r"(a) : "l"(p));
    return a;
}
__device__ __forceinline__ void cp16(uint32_t saddr, const void* g) {
    asm volatile("cp.async.cg.shared.global [%0], [%1], 16;"
                 :: "r"(saddr), "l"(g));
}
#define CP_COMMIT() asm volatile("cp.async.commit_group;" ::: "memory")
#define CP_WAIT(n)  asm volatile("cp.async.wait_group %0;" :: "n"(n) : "memory")

__device__ __forceinline__ void ldm_x4(uint32_t* r, uint32_t addr) {
    asm volatile("ldmatrix.sync.aligned.m8n8.x4.shared.b16 {%0,%1,%2,%3}, [%4];"
                 : "=r"(r[0]), "=r"(r[1]), "=r"(r[2]), "=r"(r[3]) : "r"(addr));
}
__device__ __forceinline__ void mma_s8(int* c, const uint32_t* a,
                                       const uint32_t* b) {
    asm volatile(
        "mma.sync.aligned.m16n8k32.row.col.s32.s8.s8.s32 "
        "{%0,%1,%2,%3}, {%4,%5,%6,%7}, {%8,%9}, {%0,%1,%2,%3};"
        : "+r"(c[0]), "+r"(c[1]), "+r"(c[2]), "+r"(c[3])
        : "r"(a[0]), "r"(a[1]), "r"(a[2]), "r"(a[3]), "r"(b[0]), "r"(b[1]));
}
// fp32 combine: |accA| < 2^27 -> rel err ~2^-24, negligible vs 5e-4 budget
__device__ __forceinline__ float comb2(int hi, int mid) {
    return fmaf((float)hi, 65536.f, (float)mid * 256.f);
}

// ---------------------------------------------------------------------------
// transpose x -> g_Xtf [b][n][512] fp32
// ---------------------------------------------------------------------------
__global__ __launch_bounds__(256)
void xtrans_kernel(const float* __restrict__ x)
{
    __shared__ float ts[32][33];
    const int tx = threadIdx.x, ty = threadIdx.y;
    const int n0 = blockIdx.x * 32, c0 = blockIdx.y * 32, b = blockIdx.z;
#pragma unroll
    for (int i = 0; i < 4; i++)
        ts[ty + i * 8][tx] =
            x[((size_t)(b * CIN + c0 + ty + i * 8)) * NPIX + n0 + tx];
    __syncthreads();
#pragma unroll
    for (int i = 0; i < 4; i++) {
        const int n = n0 + ty + i * 8;
        g_Xtf[((size_t)(b * NPIX + n)) * 512 + c0 + tx] = ts[tx][ty + i * 8];
    }
}

// ---------------------------------------------------------------------------
// qrows: per-row 16-bit fixed-point quantization.
// src row [K] fp32 -> dst row [d1 K | d2 K] s8, sc[row] = rowmax/32512.
// ---------------------------------------------------------------------------
__global__ __launch_bounds__(256)
void qrows_kernel(const float* __restrict__ src, int8_t* __restrict__ dst,
                  float* __restrict__ sc, int K)
{
    __shared__ float red[8];
    const int r = blockIdx.x, t = threadIdx.x;
    const float* row = src + (size_t)r * K;

    float mx = 0.f;
    for (int k = t; k < K; k += 256) mx = fmaxf(mx, fabsf(row[k]));
#pragma unroll
    for (int o = 16; o > 0; o >>= 1) mx = fmaxf(mx, __shfl_xor_sync(~0u, mx, o));
    if ((t & 31) == 0) red[t >> 5] = mx;
    __syncthreads();
    if (t < 8) {
        float v = red[t];
        v = fmaxf(v, __shfl_xor_sync(0xffu, v, 1));
        v = fmaxf(v, __shfl_xor_sync(0xffu, v, 2));
        v = fmaxf(v, __shfl_xor_sync(0xffu, v, 4));
        red[t] = v;
    }
    __syncthreads();
    mx = red[0];
    const float q = (mx > 0.f) ? 32512.f / mx : 0.f;
    if (t == 0) sc[r] = mx * (1.f / 32512.f);

    int8_t* d1p = dst + (size_t)r * (2 * K);
    for (int k = t; k < K; k += 256) {
        int d  = __float2int_rn(row[k] * q);
        int d1 = (d + 128) >> 8;
        d1p[k]     = (int8_t)d1;
        d1p[K + k] = (int8_t)(d - (d1 << 8));
    }
}

// ---------------------------------------------------------------------------
// Unified int8 GEMM. D[m][n] = sum_k A[m][k] B[n][k], rows [d1 K|d2 K] s8.
// CTA 128m x 64n, k-chunk 128, double buffer (2x48KB). 8 warps, warp tile
// 32x32, occupancy 2 (regs <= 128). accA = d1e1 (w 65536), accB = d1e2+d2e1
// (w 256); d2e2 dropped.
// WHICH=0: A=g_Kd(j), B=g_Qd(i) -> g_E fp32
// WHICH=1: A=g_Pd(i), B=g_Vd(c) -> out fp32
// WHICH=2: A=g_Wd(o), B=g_Xtd(n) -> +bias -> g_Qf/g_Kf ([b][n][o]), g_Vf ([b][c][n])
// ---------------------------------------------------------------------------
template <int WHICH>
__global__ void __launch_bounds__(256, 2)
gemm_s8_kernel(float* __restrict__ Dout,
               const float* __restrict__ fb, const float* __restrict__ gb,
               const float* __restrict__ hb)
{
    extern __shared__ __align__(1024) char smc[];
    const uint32_t smb = smem_u32(smc);

    const int t   = threadIdx.x;
    const int wid = t >> 5;
    const int lt  = t & 31;
    const int mBase = blockIdx.x * 128;
    const int nBase = blockIdx.y * 64;
    const int b     = blockIdx.z;

    const int8_t* Ab; const int8_t* Bb;
    const float* sAv; const float* sBv;
    int kchunks;
    if (WHICH == 0) {
        Ab = g_Kd + (size_t)b * NPIX * 512;
        Bb = g_Qd + (size_t)b * NPIX * 512;
        sAv = g_Ksc + (size_t)b * NPIX;
        sBv = g_Qsc + (size_t)b * NPIX;
        kchunks = 2;
    } else if (WHICH == 1) {
        Ab = g_Pd + (size_t)b * NPIX * 8192;
        Bb = g_Vd + (size_t)b * CV * 8192;
        sAv = g_Psc + (size_t)b * NPIX;
        sBv = g_Vsc + (size_t)b * CV;
        kchunks = 32;
    } else {
        Ab = g_Wd;
        Bb = g_Xtd + (size_t)b * NPIX * 1024;
        sAv = g_Wsc;
        sBv = g_Xsc + (size_t)b * NPIX;
        kchunks = 4;
    }
    const int Koff    = kchunks * 128;   // digit-2 offset within a row
    const int strideA = Koff * 2;        // bytes per row

    // 8 warps: 4 m-warps x 2 n-warps, warp tile 32x32
    const int m0 = (wid >> 1) * 32;
    const int n0 = (wid & 1) * 32;
    const int aRow  = (lt & 7) + ((lt >> 3) & 1) * 8;
    const int aByte = ((lt >> 4) & 1) * 16;
    const int bRow  = (lt & 7) + ((lt >> 4) & 1) * 8;
    const int bByte = ((lt >> 3) & 1) * 16;

    int accA[2][4][4], accB[2][4][4];
#pragma unroll
    for (int i = 0; i < 2; i++)
#pragma unroll
        for (int j = 0; j < 4; j++)
#pragma unroll
            for (int r = 0; r < 4; r++) { accA[i][j][r] = 0; accB[i][j][r] = 0; }

    // chunk buffer: A1 @0 (16K), A2 @16K, B1 @32K (8K), B2 @40960; 48KB/chunk
    auto load_chunk = [&](int cc, int buf) {
        const uint32_t base = (uint32_t)buf * 49152u;
        const int k0 = cc * 128;
#pragma unroll
        for (int i = 0; i < 4; i++) {
            int u = t + i * 256;
            int row = u >> 3, c16 = u & 7;
            uint32_t sw = SWZ128(row * 128 + c16 * 16);
            const int8_t* gp = Ab + (size_t)(mBase + row) * strideA + k0 + c16 * 16;
            cp16(smb + base + sw, gp);
            cp16(smb + base + 16384u + sw, gp + Koff);
        }
#pragma unroll
        for (int i = 0; i < 2; i++) {
            int u = t + i * 256;
            int row = u >> 3, c16 = u & 7;
            uint32_t sw = SWZ128(row * 128 + c16 * 16);
            const int8_t* gp = Bb + (size_t)(nBase + row) * strideA + k0 + c16 * 16;
            cp16(smb + base + 32768u + sw, gp);
            cp16(smb + base + 40960u + sw, gp + Koff);
        }
        CP_COMMIT();
    };

    load_chunk(0, 0);
    for (int cc = 0; cc < kchunks; cc++) {
        if (cc + 1 < kchunks) { load_chunk(cc + 1, (cc + 1) & 1); CP_WAIT(1); }
        else                  { CP_WAIT(0); }
        __syncthreads();

        const uint32_t ba  = (uint32_t)(cc & 1) * 49152u;
        const uint32_t oA1 = ba, oA2 = ba + 16384u;
        const uint32_t oB1 = ba + 32768u, oB2 = ba + 40960u;

#pragma unroll
        for (int kq = 0; kq < 4; kq++) {
            const int kb = kq * 32;                // 32 bytes = k32 step
            uint32_t a1[2][4], a2[2][4], b1[2][4], b2[2][4];
#pragma unroll
            for (int im = 0; im < 2; im++) {
                uint32_t sw = SWZ128((m0 + im * 16 + aRow) * 128 + kb + aByte);
                ldm_x4(a1[im], smb + oA1 + sw);
                ldm_x4(a2[im], smb + oA2 + sw);
            }
#pragma unroll
            for (int jp = 0; jp < 2; jp++) {
                uint32_t sw = SWZ128((n0 + jp * 16 + bRow) * 128 + kb + bByte);
                ldm_x4(b1[jp], smb + oB1 + sw);
                ldm_x4(b2[jp], smb + oB2 + sw);
            }
#pragma unroll
            for (int im = 0; im < 2; im++)
#pragma unroll
                for (int jn = 0; jn < 4; jn++) {
                    const uint32_t* e1 = &b1[jn >> 1][(jn & 1) * 2];
                    const uint32_t* e2 = &b2[jn >> 1][(jn & 1) * 2];
                    mma_s8(accA[im][jn], a1[im], e1);
                    mma_s8(accB[im][jn], a1[im], e2);
                    mma_s8(accB[im][jn], a2[im], e1);
                }
        }
        __syncthreads();
    }

    const int cr   = lt >> 2;
    const int ccol = 2 * (lt & 3);

    if (WHICH <= 1) {
        float* sC = (float*)smc;   // [64 n][132 m]
#pragma unroll
        for (int im = 0; im < 2; im++) {
            const int m = m0 + im * 16 + cr;
            const float sa0 = sAv[mBase + m], sa1 = sAv[mBase + m + 8];
#pragma unroll
            for (int jn = 0; jn < 4; jn++) {
                const int n = n0 + jn * 8 + ccol;
                const float sb0 = sBv[nBase + n], sb1 = sBv[nBase + n + 1];
                sC[n * 132 + m]           = comb2(accA[im][jn][0], accB[im][jn][0]) * (sa0 * sb0);
                sC[(n + 1) * 132 + m]     = comb2(accA[im][jn][1], accB[im][jn][1]) * (sa0 * sb1);
                sC[n * 132 + m + 8]       = comb2(accA[im][jn][2], accB[im][jn][2]) * (sa1 * sb0);
                sC[(n + 1) * 132 + m + 8] = comb2(accA[im][jn][3], accB[im][jn][3]) * (sa1 * sb1);
            }
        }
        __syncthreads();
        float* Db = (WHICH == 0) ? g_E + (size_t)b * NPIX * NPIX
                                 : Dout + (size_t)b * CV * NPIX;
#pragma unroll
        for (int i = 0; i < 8; i++) {
            int idx = t + i * 256;
            int n = idx >> 5, m4 = (idx & 31) << 2;
            float4 v = *(const float4*)(sC + n * 132 + m4);
            *(float4*)(Db + (size_t)(nBase + n) * NPIX + mBase + m4) = v;
        }
    } else {
        const float* bsel; int o0;
        if (mBase < 256)      { bsel = fb; o0 = mBase; }
        else if (mBase < 512) { bsel = gb; o0 = mBase - 256; }
        else                  { bsel = hb; o0 = mBase - 512; }

        if (mBase < 512) {
            float* sC = (float*)smc;   // [64 n][132 m]
#pragma unroll
            for (int im = 0; im < 2; im++) {
                const int m = m0 + im * 16 + cr;
                const float sa0 = sAv[mBase + m], sa1 = sAv[mBase + m + 8];
                const float bi0 = bsel[o0 + m], bi1 = bsel[o0 + m + 8];
#pragma unroll
                for (int jn = 0; jn < 4; jn++) {
                    const int n = n0 + jn * 8 + ccol;
                    const float sb0 = sBv[nBase + n], sb1 = sBv[nBase + n + 1];
                    sC[n * 132 + m]           = comb2(accA[im][jn][0], accB[im][jn][0]) * (sa0 * sb0) + bi0;
                    sC[(n + 1) * 132 + m]     = comb2(accA[im][jn][1], accB[im][jn][1]) * (sa0 * sb1) + bi0;
                    sC[n * 132 + m + 8]       = comb2(accA[im][jn][2], accB[im][jn][2]) * (sa1 * sb0) + bi1;
                    sC[(n + 1) * 132 + m + 8] = comb2(accA[im][jn][3], accB[im][jn][3]) * (sa1 * sb1) + bi1;
                }
            }
            __syncthreads();
            float* dst = (mBase < 256) ? g_Qf : g_Kf;
            const int oc0 = mBase & 255;   // 0 or 128
#pragma unroll
            for (int i = 0; i < 8; i++) {
                int idx = t + i * 256;
                int n = idx >> 5, m4 = (idx & 31) << 2;
                float4 v = *(const float4*)(sC + n * 132 + m4);
                *(float4*)(dst + ((size_t)(b * NPIX + nBase + n)) * 256 + oc0 + m4) = v;
            }
        } else {
            float* sC = (float*)smc;   // [128 m][68 n]
#pragma unroll
            for (int im = 0; im < 2; im++) {
                const int m = m0 + im * 16 + cr;
                const float sa0 = sAv[mBase + m], sa1 = sAv[mBase + m + 8];
                const float bi0 = bsel[o0 + m], bi1 = bsel[o0 + m + 8];
#pragma unroll
                for (int jn = 0; jn < 4; jn++) {
                    const int n = n0 + jn * 8 + ccol;
                    const float sb0 = sBv[nBase + n], sb1 = sBv[nBase + n + 1];
                    sC[m * 68 + n]           = comb2(accA[im][jn][0], accB[im][jn][0]) * (sa0 * sb0) + bi0;
                    sC[m * 68 + n + 1]       = comb2(accA[im][jn][1], accB[im][jn][1]) * (sa0 * sb1) + bi0;
                    sC[(m + 8) * 68 + n]     = comb2(accA[im][jn][2], accB[im][jn][2]) * (sa1 * sb0) + bi1;
                    sC[(m + 8) * 68 + n + 1] = comb2(accA[im][jn][3], accB[im][jn][3]) * (sa1 * sb1) + bi1;
                }
            }
            __syncthreads();
#pragma unroll
            for (int i = 0; i < 8; i++) {
                int idx = t + i * 256;
                int m = idx >> 4, n4 = (idx & 15) << 2;
                float4 v = *(const float4*)(sC + m * 68 + n4);
                *(float4*)(g_Vf + ((size_t)(b * CV + o0 + m)) * 4096 + nBase + n4) = v;
            }
        }
    }
}

// ---------------------------------------------------------------------------
// softmax: row softmax over E -> P digits (d = rint(e * 32512)), scale.
// ---------------------------------------------------------------------------
__global__ __launch_bounds__(256)
void softmax_kernel()
{
    __shared__ float red[8];
    const int i = blockIdx.x, b = blockIdx.y, t = threadIdx.x;
    const float* row = g_E + ((size_t)(b * NPIX + i)) * NPIX;

    float4 v[4];
#pragma unroll
    for (int r = 0; r < 4; r++) v[r] = ((const float4*)row)[t + r * 256];

    float m = -1e30f;
#pragma unroll
    for (int r = 0; r < 4; r++)
        m = fmaxf(m, fmaxf(fmaxf(v[r].x, v[r].y), fmaxf(v[r].z, v[r].w)));
#pragma unroll
    for (int o = 16; o > 0; o >>= 1) m = fmaxf(m, __shfl_xor_sync(~0u, m, o));
    if ((t & 31) == 0) red[t >> 5] = m;
    __syncthreads();
    if (t < 8) {
        float x2 = red[t];
        x2 = fmaxf(x2, __shfl_xor_sync(0xffu, x2, 1));
        x2 = fmaxf(x2, __shfl_xor_sync(0xffu, x2, 2));
        x2 = fmaxf(x2, __shfl_xor_sync(0xffu, x2, 4));
        red[t] = x2;
    }
    __syncthreads();
    m = red[0];
    __syncthreads();

    float e[16];
    float ssum = 0.f;
#pragma unroll
    for (int r = 0; r < 4; r++) {
        e[r * 4 + 0] = __expf(v[r].x - m);
        e[r * 4 + 1] = __expf(v[r].y - m);
        e[r * 4 + 2] = __expf(v[r].z - m);
        e[r * 4 + 3] = __expf(v[r].w - m);
        ssum += (e[r*4+0] + e[r*4+1]) + (e[r*4+2] + e[r*4+3]);
    }
#pragma unroll
    for (int o = 16; o > 0; o >>= 1) ssum += __shfl_xor_sync(~0u, ssum, o);
    if ((t & 31) == 0) red[t >> 5] = ssum;
    __syncthreads();
    if (t < 8) {
        float x2 = red[t];
        x2 += __shfl_xor_sync(0xffu, x2, 1);
        x2 += __shfl_xor_sync(0xffu, x2, 2);
        x2 += __shfl_xor_sync(0xffu, x2, 4);
        red[t] = x2;
    }
    __syncthreads();
    const float inv = 1.f / red[0];
    if (t == 0) g_Psc[(size_t)b * NPIX + i] = inv * (1.f / 32512.f);

    int8_t* pb = g_Pd + ((size_t)(b * NPIX + i)) * 8192;
#pragma unroll
    for (int r = 0; r < 4; r++) {
        const int j0 = (t + r * 256) * 4;
        char d1v[4], d2v[4];
#pragma unroll
        for (int k = 0; k < 4; k++) {
            int d  = __float2int_rn(e[r * 4 + k] * 32512.f);
            int d1 = (d + 128) >> 8;
            d1v[k] = (char)d1;
            d2v[k] = (char)(d - (d1 << 8));
        }
        *(char4*)(pb + j0)        = make_char4(d1v[0], d1v[1], d1v[2], d1v[3]);
        *(char4*)(pb + 4096 + j0) = make_char4(d2v[0], d2v[1], d2v[2], d2v[3]);
    }
}

// ---------------------------------------------------------------------------
extern "C" void kernel_launch(void* const* d_in, const int* in_sizes, int n_in,
                              void* d_out, int out_size)
{
    const float* x   = (const float*)d_in[0];
    const float* f_w = (const float*)d_in[1];
    const float* f_b = (const float*)d_in[2];
    const float* g_w = (const float*)d_in[3];
    const float* g_b = (const float*)d_in[4];
    const float* h_w = (const float*)d_in[5];
    const float* h_b = (const float*)d_in[6];
    float* out = (float*)d_out;
    (void)in_sizes; (void)n_in; (void)out_size;

    cudaFuncSetAttribute(gemm_s8_kernel<0>,
                         cudaFuncAttributeMaxDynamicSharedMemorySize, SME);
    cudaFuncSetAttribute(gemm_s8_kernel<1>,
                         cudaFuncAttributeMaxDynamicSharedMemorySize, SME);
    cudaFuncSetAttribute(gemm_s8_kernel<2>,
                         cudaFuncAttributeMaxDynamicSharedMemorySize, SME);

    int8_t* wd; float* wsc; float* xtf; int8_t* xtd; float* xsc;
    cudaGetSymbolAddress((void**)&wd,  g_Wd);
    cudaGetSymbolAddress((void**)&wsc, g_Wsc);
    cudaGetSymbolAddress((void**)&xtf, g_Xtf);
    cudaGetSymbolAddress((void**)&xtd, g_Xtd);
    cudaGetSymbolAddress((void**)&xsc, g_Xsc);
    float* qf; float* kf; float* vf;
    int8_t* qd; int8_t* kd; int8_t* vd;
    float* qsc; float* ksc; float* vsc;
    cudaGetSymbolAddress((void**)&qf, g_Qf);  cudaGetSymbolAddress((void**)&kf, g_Kf);
    cudaGetSymbolAddress((void**)&vf, g_Vf);
    cudaGetSymbolAddress((void**)&qd, g_Qd);  cudaGetSymbolAddress((void**)&kd, g_Kd);
    cudaGetSymbolAddress((void**)&vd, g_Vd);
    cudaGetSymbolAddress((void**)&qsc, g_Qsc); cudaGetSymbolAddress((void**)&ksc, g_Ksc);
    cudaGetSymbolAddress((void**)&vsc, g_Vsc);

    // quantize weights (rows contiguous per matrix; o stacked [f|g|h])
    qrows_kernel<<<256, 256>>>(f_w, wd,                 wsc,       512);
    qrows_kernel<<<256, 256>>>(g_w, wd + 256 * 1024,    wsc + 256, 512);
    qrows_kernel<<<512, 256>>>(h_w, wd + 512 * 1024,    wsc + 512, 512);
    // x^T then quantize pixel rows
    xtrans_kernel<<<dim3(NPIX / 32, CIN / 32, BATCH), dim3(32, 8)>>>(x);
    qrows_kernel<<<BATCH * NPIX, 256>>>(xtf, xtd, xsc, 512);
    // proj GEMM -> fp32 Q/K/V
    gemm_s8_kernel<2><<<dim3(8, 64, 4), 256, SME>>>(nullptr, f_b, g_b, h_b);
    // quantize Q/K/V rows
    qrows_kernel<<<BATCH * NPIX, 256>>>(qf, qd, qsc, 256);
    qrows_kernel<<<BATCH * NPIX, 256>>>(kf, kd, ksc, 256);
    qrows_kernel<<<BATCH * CV,   256>>>(vf, vd, vsc, 4096);
    // E = Q.K^T
    gemm_s8_kernel<0><<<dim3(32, 64, 4), 256, SME>>>(nullptr, f_b, g_b, h_b);
    // softmax -> P digits
    softmax_kernel<<<dim3(NPIX, BATCH), 256>>>();
    // out = P.V^T
    gemm_s8_kernel<1><<<dim3(32, 8, 4), 256, SME>>>(out, f_b, g_b, h_b);
}

// round 10
// speedup vs baseline: 6.9589x; 1.0020x over previous
#include <cuda_runtime.h>
#include <cuda_bf16.h>
#include <cstdint>

// ---------------------------------------------------------------------------
// SAGAN self-attention, B=4, C=512, H=W=64 (N=4096), fp32 in/out.
// R10: int8 tensor-core pipeline (mma.sync m16n8k32 s8.s8.s32), 16-bit
// fixed-point rowwise quantization v = s*(256*d1 + d2), 3-product scheme
// (d2e2 dropped). GEMM tiles now templated (MT x NT): PV uses 64x128 to
// halve DRAM re-reads of the P digit matrix; E/proj keep 128x64. Occ 2.
//   xtrans   : x^T -> g_Xtf fp32
//   qrows    : rowwise quantize -> digits + scale
//   gemm<2>  : proj (W x Xt) + bias -> g_Qf/g_Kf/g_Vf fp32
//   gemm<0>  : E = Q.K^T -> g_E fp32
//   softmax  : P = softmax(E) -> digits g_Pd + scale
//   gemm<1>  : out = P.V^T
// ---------------------------------------------------------------------------

#define BATCH 4
#define NPIX  4096
#define CIN   512
#define CV    512
#define SME   98304    // 2 x 48KB chunk buffers; epilogue reuses < 35KB

// fp32 staging
__device__ __align__(16) float  g_Xtf[(size_t)BATCH * NPIX * 512];
__device__ __align__(16) float  g_Qf [(size_t)BATCH * NPIX * 256];
__device__ __align__(16) float  g_Kf [(size_t)BATCH * NPIX * 256];
__device__ __align__(16) float  g_Vf [(size_t)BATCH * CV   * 4096];
__device__ __align__(16) float  g_E  [(size_t)BATCH * NPIX * NPIX];
// digit buffers: rows stored [d1 K | d2 K]
__device__ __align__(16) int8_t g_Wd [(size_t)1024 * 1024];
__device__ __align__(16) int8_t g_Xtd[(size_t)BATCH * NPIX * 1024];
__device__ __align__(16) int8_t g_Qd [(size_t)BATCH * NPIX * 512];
__device__ __align__(16) int8_t g_Kd [(size_t)BATCH * NPIX * 512];
__device__ __align__(16) int8_t g_Vd [(size_t)BATCH * CV   * 8192];
__device__ __align__(16) int8_t g_Pd [(size_t)BATCH * NPIX * 8192];
// row scales
__device__ float g_Wsc [1024];
__device__ float g_Xsc [(size_t)BATCH * NPIX];
__device__ float g_Qsc [(size_t)BATCH * NPIX];
__device__ float g_Ksc [(size_t)BATCH * NPIX];
__device__ float g_Vsc [(size_t)BATCH * CV];
__device__ float g_Psc [(size_t)BATCH * NPIX];

#define SWZ128(x) ((x) ^ (((x) >> 3) & 0x70))

__device__ __forceinline__ uint32_t smem_u32(const void* p) {
    uint32_t a;
    asm("{ .reg .u64 t; cvta.to.shared.u64 t, %1; cvt.u32.u64 %0, t; }"
        : "=r"(a) : "l"(p));
    return a;
}
__device__ __forceinline__ void cp16(uint32_t saddr, const void* g) {
    asm volatile("cp.async.cg.shared.global [%0], [%1], 16;"
                 :: "r"(saddr), "l"(g));
}
#define CP_COMMIT() asm volatile("cp.async.commit_group;" ::: "memory")
#define CP_WAIT(n)  asm volatile("cp.async.wait_group %0;" :: "n"(n) : "memory")

__device__ __forceinline__ void ldm_x4(uint32_t* r, uint32_t addr) {
    asm volatile("ldmatrix.sync.aligned.m8n8.x4.shared.b16 {%0,%1,%2,%3}, [%4];"
                 : "=r"(r[0]), "=r"(r[1]), "=r"(r[2]), "=r"(r[3]) : "r"(addr));
}
__device__ __forceinline__ void mma_s8(int* c, const uint32_t* a,
                                       const uint32_t* b) {
    asm volatile(
        "mma.sync.aligned.m16n8k32.row.col.s32.s8.s8.s32 "
        "{%0,%1,%2,%3}, {%4,%5,%6,%7}, {%8,%9}, {%0,%1,%2,%3};"
        : "+r"(c[0]), "+r"(c[1]), "+r"(c[2]), "+r"(c[3])
        : "r"(a[0]), "r"(a[1]), "r"(a[2]), "r"(a[3]), "r"(b[0]), "r"(b[1]));
}
// fp32 combine: |accA| < 2^27 -> rel err ~2^-24, negligible vs 5e-4 budget
__device__ __forceinline__ float comb2(int hi, int mid) {
    return fmaf((float)hi, 65536.f, (float)mid * 256.f);
}

// ---------------------------------------------------------------------------
// transpose x -> g_Xtf [b][n][512] fp32
// ---------------------------------------------------------------------------
__global__ __launch_bounds__(256)
void xtrans_kernel(const float* __restrict__ x)
{
    __shared__ float ts[32][33];
    const int tx = threadIdx.x, ty = threadIdx.y;
    const int n0 = blockIdx.x * 32, c0 = blockIdx.y * 32, b = blockIdx.z;
#pragma unroll
    for (int i = 0; i < 4; i++)
        ts[ty + i * 8][tx] =
            x[((size_t)(b * CIN + c0 + ty + i * 8)) * NPIX + n0 + tx];
    __syncthreads();
#pragma unroll
    for (int i = 0; i < 4; i++) {
        const int n = n0 + ty + i * 8;
        g_Xtf[((size_t)(b * NPIX + n)) * 512 + c0 + tx] = ts[tx][ty + i * 8];
    }
}

// ---------------------------------------------------------------------------
// qrows: per-row 16-bit fixed-point quantization.
// src row [K] fp32 -> dst row [d1 K | d2 K] s8, sc[row] = rowmax/32512.
// ---------------------------------------------------------------------------
__global__ __launch_bounds__(256)
void qrows_kernel(const float* __restrict__ src, int8_t* __restrict__ dst,
                  float* __restrict__ sc, int K)
{
    __shared__ float red[8];
    const int r = blockIdx.x, t = threadIdx.x;
    const float* row = src + (size_t)r * K;

    float mx = 0.f;
    for (int k = t; k < K; k += 256) mx = fmaxf(mx, fabsf(row[k]));
#pragma unroll
    for (int o = 16; o > 0; o >>= 1) mx = fmaxf(mx, __shfl_xor_sync(~0u, mx, o));
    if ((t & 31) == 0) red[t >> 5] = mx;
    __syncthreads();
    if (t < 8) {
        float v = red[t];
        v = fmaxf(v, __shfl_xor_sync(0xffu, v, 1));
        v = fmaxf(v, __shfl_xor_sync(0xffu, v, 2));
        v = fmaxf(v, __shfl_xor_sync(0xffu, v, 4));
        red[t] = v;
    }
    __syncthreads();
    mx = red[0];
    const float q = (mx > 0.f) ? 32512.f / mx : 0.f;
    if (t == 0) sc[r] = mx * (1.f / 32512.f);

    int8_t* d1p = dst + (size_t)r * (2 * K);
    for (int k = t; k < K; k += 256) {
        int d  = __float2int_rn(row[k] * q);
        int d1 = (d + 128) >> 8;
        d1p[k]     = (int8_t)d1;
        d1p[K + k] = (int8_t)(d - (d1 << 8));
    }
}

// ---------------------------------------------------------------------------
// Unified int8 GEMM, tile-shape templated. D[m][n] = sum_k A[m][k] B[n][k],
// rows [d1 K|d2 K] s8. CTA MT x NT (MT+NT == 192 -> 48KB chunk, 2x buffered,
// occupancy 2). 8 warps, warp tile 32x32. accA = d1e1 (w 65536),
// accB = d1e2+d2e1 (w 256); d2e2 dropped.
// WHICH=0 (128x64): A=g_Kd(j), B=g_Qd(i) -> g_E fp32
// WHICH=1 (64x128): A=g_Pd(i), B=g_Vd(c) -> out fp32
// WHICH=2 (128x64): A=g_Wd(o), B=g_Xtd(n) -> +bias -> g_Qf/g_Kf/g_Vf
// ---------------------------------------------------------------------------
template <int WHICH, int MT, int NT>
__global__ void __launch_bounds__(256, 2)
gemm_s8_kernel(float* __restrict__ Dout,
               const float* __restrict__ fb, const float* __restrict__ gb,
               const float* __restrict__ hb)
{
    static_assert(MT + NT == 192, "chunk sized for 48KB");
    extern __shared__ __align__(1024) char smc[];
    const uint32_t smb = smem_u32(smc);

    const int t   = threadIdx.x;
    const int wid = t >> 5;
    const int lt  = t & 31;
    const int mBase = blockIdx.x * MT;
    const int nBase = blockIdx.y * NT;
    const int b     = blockIdx.z;

    const int8_t* Ab; const int8_t* Bb;
    const float* sAv; const float* sBv;
    int kchunks;
    if (WHICH == 0) {
        Ab = g_Kd + (size_t)b * NPIX * 512;
        Bb = g_Qd + (size_t)b * NPIX * 512;
        sAv = g_Ksc + (size_t)b * NPIX;
        sBv = g_Qsc + (size_t)b * NPIX;
        kchunks = 2;
    } else if (WHICH == 1) {
        Ab = g_Pd + (size_t)b * NPIX * 8192;
        Bb = g_Vd + (size_t)b * CV * 8192;
        sAv = g_Psc + (size_t)b * NPIX;
        sBv = g_Vsc + (size_t)b * CV;
        kchunks = 32;
    } else {
        Ab = g_Wd;
        Bb = g_Xtd + (size_t)b * NPIX * 1024;
        sAv = g_Wsc;
        sBv = g_Xsc + (size_t)b * NPIX;
        kchunks = 4;
    }
    const int Koff    = kchunks * 128;   // digit-2 offset within a row
    const int strideA = Koff * 2;        // bytes per row

    // 8 warps: (MT/32) m-warps x (NT/32) n-warps, warp tile 32x32
    constexpr int NW = NT / 32;
    const int m0 = (wid / NW) * 32;
    const int n0 = (wid % NW) * 32;
    const int aRow  = (lt & 7) + ((lt >> 3) & 1) * 8;
    const int aByte = ((lt >> 4) & 1) * 16;
    const int bRow  = (lt & 7) + ((lt >> 4) & 1) * 8;
    const int bByte = ((lt >> 3) & 1) * 16;

    int accA[2][4][4], accB[2][4][4];
#pragma unroll
    for (int i = 0; i < 2; i++)
#pragma unroll
        for (int j = 0; j < 4; j++)
#pragma unroll
            for (int r = 0; r < 4; r++) { accA[i][j][r] = 0; accB[i][j][r] = 0; }

    // chunk layout: A1 @0, A2 @MT*128, B1 @2*MT*128, B2 @2*MT*128+NT*128
    constexpr uint32_t OA2 = (uint32_t)MT * 128u;
    constexpr uint32_t OB1 = 2u * MT * 128u;
    constexpr uint32_t OB2 = OB1 + (uint32_t)NT * 128u;
    auto load_chunk = [&](int cc, int buf) {
        const uint32_t base = (uint32_t)buf * 49152u;
        const int k0 = cc * 128;
#pragma unroll
        for (int i = 0; i < MT / 32; i++) {
            int u = t + i * 256;
            int row = u >> 3, c16 = u & 7;
            uint32_t sw = SWZ128(row * 128 + c16 * 16);
            const int8_t* gp = Ab + (size_t)(mBase + row) * strideA + k0 + c16 * 16;
            cp16(smb + base + sw, gp);
            cp16(smb + base + OA2 + sw, gp + Koff);
        }
#pragma unroll
        for (int i = 0; i < NT / 32; i++) {
            int u = t + i * 256;
            int row = u >> 3, c16 = u & 7;
            uint32_t sw = SWZ128(row * 128 + c16 * 16);
            const int8_t* gp = Bb + (size_t)(nBase + row) * strideA + k0 + c16 * 16;
            cp16(smb + base + OB1 + sw, gp);
            cp16(smb + base + OB2 + sw, gp + Koff);
        }
        CP_COMMIT();
    };

    load_chunk(0, 0);
    for (int cc = 0; cc < kchunks; cc++) {
        if (cc + 1 < kchunks) { load_chunk(cc + 1, (cc + 1) & 1); CP_WAIT(1); }
        else                  { CP_WAIT(0); }
        __syncthreads();

        const uint32_t ba  = (uint32_t)(cc & 1) * 49152u;
        const uint32_t oA1 = ba, oA2 = ba + OA2;
        const uint32_t oB1 = ba + OB1, oB2 = ba + OB2;

#pragma unroll
        for (int kq = 0; kq < 4; kq++) {
            const int kb = kq * 32;                // 32 bytes = k32 step
            uint32_t a1[2][4], a2[2][4], b1[2][4], b2[2][4];
#pragma unroll
            for (int im = 0; im < 2; im++) {
                uint32_t sw = SWZ128((m0 + im * 16 + aRow) * 128 + kb + aByte);
                ldm_x4(a1[im], smb + oA1 + sw);
                ldm_x4(a2[im], smb + oA2 + sw);
            }
#pragma unroll
            for (int jp = 0; jp < 2; jp++) {
                uint32_t sw = SWZ128((n0 + jp * 16 + bRow) * 128 + kb + bByte);
                ldm_x4(b1[jp], smb + oB1 + sw);
                ldm_x4(b2[jp], smb + oB2 + sw);
            }
#pragma unroll
            for (int im = 0; im < 2; im++)
#pragma unroll
                for (int jn = 0; jn < 4; jn++) {
                    const uint32_t* e1 = &b1[jn >> 1][(jn & 1) * 2];
                    const uint32_t* e2 = &b2[jn >> 1][(jn & 1) * 2];
                    mma_s8(accA[im][jn], a1[im], e1);
                    mma_s8(accB[im][jn], a1[im], e2);
                    mma_s8(accB[im][jn], a2[im], e1);
                }
        }
        __syncthreads();
    }

    const int cr   = lt >> 2;
    const int ccol = 2 * (lt & 3);
    constexpr int SCT = MT + 4;

    if (WHICH <= 1) {
        float* sC = (float*)smc;   // [NT n][MT+4 m]
#pragma unroll
        for (int im = 0; im < 2; im++) {
            const int m = m0 + im * 16 + cr;
            const float sa0 = sAv[mBase + m], sa1 = sAv[mBase + m + 8];
#pragma unroll
            for (int jn = 0; jn < 4; jn++) {
                const int n = n0 + jn * 8 + ccol;
                const float sb0 = sBv[nBase + n], sb1 = sBv[nBase + n + 1];
                sC[n * SCT + m]           = comb2(accA[im][jn][0], accB[im][jn][0]) * (sa0 * sb0);
                sC[(n + 1) * SCT + m]     = comb2(accA[im][jn][1], accB[im][jn][1]) * (sa0 * sb1);
                sC[n * SCT + m + 8]       = comb2(accA[im][jn][2], accB[im][jn][2]) * (sa1 * sb0);
                sC[(n + 1) * SCT + m + 8] = comb2(accA[im][jn][3], accB[im][jn][3]) * (sa1 * sb1);
            }
        }
        __syncthreads();
        float* Db = (WHICH == 0) ? g_E + (size_t)b * NPIX * NPIX
                                 : Dout + (size_t)b * CV * NPIX;
        constexpr int M4 = MT / 4;
#pragma unroll
        for (int i = 0; i < (NT * M4) / 256; i++) {
            int idx = t + i * 256;
            int n = idx / M4, m4 = (idx % M4) * 4;
            float4 v = *(const float4*)(sC + n * SCT + m4);
            *(float4*)(Db + (size_t)(nBase + n) * NPIX + mBase + m4) = v;
        }
    } else {
        const float* bsel; int o0;
        if (mBase < 256)      { bsel = fb; o0 = mBase; }
        else if (mBase < 512) { bsel = gb; o0 = mBase - 256; }
        else                  { bsel = hb; o0 = mBase - 512; }

        if (mBase < 512) {
            float* sC = (float*)smc;   // [NT n][MT+4 m]
#pragma unroll
            for (int im = 0; im < 2; im++) {
                const int m = m0 + im * 16 + cr;
                const float sa0 = sAv[mBase + m], sa1 = sAv[mBase + m + 8];
                const float bi0 = bsel[o0 + m], bi1 = bsel[o0 + m + 8];
#pragma unroll
                for (int jn = 0; jn < 4; jn++) {
                    const int n = n0 + jn * 8 + ccol;
                    const float sb0 = sBv[nBase + n], sb1 = sBv[nBase + n + 1];
                    sC[n * SCT + m]           = comb2(accA[im][jn][0], accB[im][jn][0]) * (sa0 * sb0) + bi0;
                    sC[(n + 1) * SCT + m]     = comb2(accA[im][jn][1], accB[im][jn][1]) * (sa0 * sb1) + bi0;
                    sC[n * SCT + m + 8]       = comb2(accA[im][jn][2], accB[im][jn][2]) * (sa1 * sb0) + bi1;
                    sC[(n + 1) * SCT + m + 8] = comb2(accA[im][jn][3], accB[im][jn][3]) * (sa1 * sb1) + bi1;
                }
            }
            __syncthreads();
            float* dst = (mBase < 256) ? g_Qf : g_Kf;
            const int oc0 = mBase & 255;   // 0 or 128
#pragma unroll
            for (int i = 0; i < 8; i++) {
                int idx = t + i * 256;
                int n = idx >> 5, m4 = (idx & 31) << 2;
                float4 v = *(const float4*)(sC + n * SCT + m4);
                *(float4*)(dst + ((size_t)(b * NPIX + nBase + n)) * 256 + oc0 + m4) = v;
            }
        } else {
            float* sC = (float*)smc;   // [MT m][NT+4 n]
#pragma unroll
            for (int im = 0; im < 2; im++) {
                const int m = m0 + im * 16 + cr;
                const float sa0 = sAv[mBase + m], sa1 = sAv[mBase + m + 8];
                const float bi0 = bsel[o0 + m], bi1 = bsel[o0 + m + 8];
#pragma unroll
                for (int jn = 0; jn < 4; jn++) {
                    const int n = n0 + jn * 8 + ccol;
                    const float sb0 = sBv[nBase + n], sb1 = sBv[nBase + n + 1];
                    sC[m * 68 + n]           = comb2(accA[im][jn][0], accB[im][jn][0]) * (sa0 * sb0) + bi0;
                    sC[m * 68 + n + 1]       = comb2(accA[im][jn][1], accB[im][jn][1]) * (sa0 * sb1) + bi0;
                    sC[(m + 8) * 68 + n]     = comb2(accA[im][jn][2], accB[im][jn][2]) * (sa1 * sb0) + bi1;
                    sC[(m + 8) * 68 + n + 1] = comb2(accA[im][jn][3], accB[im][jn][3]) * (sa1 * sb1) + bi1;
                }
            }
            __syncthreads();
#pragma unroll
            for (int i = 0; i < 8; i++) {
                int idx = t + i * 256;
                int m = idx >> 4, n4 = (idx & 15) << 2;
                float4 v = *(const float4*)(sC + m * 68 + n4);
                *(float4*)(g_Vf + ((size_t)(b * CV + o0 + m)) * 4096 + nBase + n4) = v;
            }
        }
    }
}

// ---------------------------------------------------------------------------
// softmax: row softmax over E -> P digits (d = rint(e * 32512)), scale.
// ---------------------------------------------------------------------------
__global__ __launch_bounds__(256)
void softmax_kernel()
{
    __shared__ float red[8];
    const int i = blockIdx.x, b = blockIdx.y, t = threadIdx.x;
    const float* row = g_E + ((size_t)(b * NPIX + i)) * NPIX;

    float4 v[4];
#pragma unroll
    for (int r = 0; r < 4; r++) v[r] = ((const float4*)row)[t + r * 256];

    float m = -1e30f;
#pragma unroll
    for (int r = 0; r < 4; r++)
        m = fmaxf(m, fmaxf(fmaxf(v[r].x, v[r].y), fmaxf(v[r].z, v[r].w)));
#pragma unroll
    for (int o = 16; o > 0; o >>= 1) m = fmaxf(m, __shfl_xor_sync(~0u, m, o));
    if ((t & 31) == 0) red[t >> 5] = m;
    __syncthreads();
    if (t < 8) {
        float x2 = red[t];
        x2 = fmaxf(x2, __shfl_xor_sync(0xffu, x2, 1));
        x2 = fmaxf(x2, __shfl_xor_sync(0xffu, x2, 2));
        x2 = fmaxf(x2, __shfl_xor_sync(0xffu, x2, 4));
        red[t] = x2;
    }
    __syncthreads();
    m = red[0];
    __syncthreads();

    float e[16];
    float ssum = 0.f;
#pragma unroll
    for (int r = 0; r < 4; r++) {
        e[r * 4 + 0] = __expf(v[r].x - m);
        e[r * 4 + 1] = __expf(v[r].y - m);
        e[r * 4 + 2] = __expf(v[r].z - m);
        e[r * 4 + 3] = __expf(v[r].w - m);
        ssum += (e[r*4+0] + e[r*4+1]) + (e[r*4+2] + e[r*4+3]);
    }
#pragma unroll
    for (int o = 16; o > 0; o >>= 1) ssum += __shfl_xor_sync(~0u, ssum, o);
    if ((t & 31) == 0) red[t >> 5] = ssum;
    __syncthreads();
    if (t < 8) {
        float x2 = red[t];
        x2 += __shfl_xor_sync(0xffu, x2, 1);
        x2 += __shfl_xor_sync(0xffu, x2, 2);
        x2 += __shfl_xor_sync(0xffu, x2, 4);
        red[t] = x2;
    }
    __syncthreads();
    const float inv = 1.f / red[0];
    if (t == 0) g_Psc[(size_t)b * NPIX + i] = inv * (1.f / 32512.f);

    int8_t* pb = g_Pd + ((size_t)(b * NPIX + i)) * 8192;
#pragma unroll
    for (int r = 0; r < 4; r++) {
        const int j0 = (t + r * 256) * 4;
        char d1v[4], d2v[4];
#pragma unroll
        for (int k = 0; k < 4; k++) {
            int d  = __float2int_rn(e[r * 4 + k] * 32512.f);
            int d1 = (d + 128) >> 8;
            d1v[k] = (char)d1;
            d2v[k] = (char)(d - (d1 << 8));
        }
        *(char4*)(pb + j0)        = make_char4(d1v[0], d1v[1], d1v[2], d1v[3]);
        *(char4*)(pb + 4096 + j0) = make_char4(d2v[0], d2v[1], d2v[2], d2v[3]);
    }
}

// ---------------------------------------------------------------------------
extern "C" void kernel_launch(void* const* d_in, const int* in_sizes, int n_in,
                              void* d_out, int out_size)
{
    const float* x   = (const float*)d_in[0];
    const float* f_w = (const float*)d_in[1];
    const float* f_b = (const float*)d_in[2];
    const float* g_w = (const float*)d_in[3];
    const float* g_b = (const float*)d_in[4];
    const float* h_w = (const float*)d_in[5];
    const float* h_b = (const float*)d_in[6];
    float* out = (float*)d_out;
    (void)in_sizes; (void)n_in; (void)out_size;

    cudaFuncSetAttribute((const void*)gemm_s8_kernel<0, 128, 64>,
                         cudaFuncAttributeMaxDynamicSharedMemorySize, SME);
    cudaFuncSetAttribute((const void*)gemm_s8_kernel<1, 64, 128>,
                         cudaFuncAttributeMaxDynamicSharedMemorySize, SME);
    cudaFuncSetAttribute((const void*)gemm_s8_kernel<2, 128, 64>,
                         cudaFuncAttributeMaxDynamicSharedMemorySize, SME);

    int8_t* wd; float* wsc; float* xtf; int8_t* xtd; float* xsc;
    cudaGetSymbolAddress((void**)&wd,  g_Wd);
    cudaGetSymbolAddress((void**)&wsc, g_Wsc);
    cudaGetSymbolAddress((void**)&xtf, g_Xtf);
    cudaGetSymbolAddress((void**)&xtd, g_Xtd);
    cudaGetSymbolAddress((void**)&xsc, g_Xsc);
    float* qf; float* kf; float* vf;
    int8_t* qd; int8_t* kd; int8_t* vd;
    float* qsc; float* ksc; float* vsc;
    cudaGetSymbolAddress((void**)&qf, g_Qf);  cudaGetSymbolAddress((void**)&kf, g_Kf);
    cudaGetSymbolAddress((void**)&vf, g_Vf);
    cudaGetSymbolAddress((void**)&qd, g_Qd);  cudaGetSymbolAddress((void**)&kd, g_Kd);
    cudaGetSymbolAddress((void**)&vd, g_Vd);
    cudaGetSymbolAddress((void**)&qsc, g_Qsc); cudaGetSymbolAddress((void**)&ksc, g_Ksc);
    cudaGetSymbolAddress((void**)&vsc, g_Vsc);

    // quantize weights (rows contiguous per matrix; o stacked [f|g|h])
    qrows_kernel<<<256, 256>>>(f_w, wd,                 wsc,       512);
    qrows_kernel<<<256, 256>>>(g_w, wd + 256 * 1024,    wsc + 256, 512);
    qrows_kernel<<<512, 256>>>(h_w, wd + 512 * 1024,    wsc + 512, 512);
    // x^T then quantize pixel rows
    xtrans_kernel<<<dim3(NPIX / 32, CIN / 32, BATCH), dim3(32, 8)>>>(x);
    qrows_kernel<<<BATCH * NPIX, 256>>>(xtf, xtd, xsc, 512);
    // proj GEMM -> fp32 Q/K/V
    gemm_s8_kernel<2, 128, 64><<<dim3(8, 64, 4), 256, SME>>>(nullptr, f_b, g_b, h_b);
    // quantize Q/K/V rows
    qrows_kernel<<<BATCH * NPIX, 256>>>(qf, qd, qsc, 256);
    qrows_kernel<<<BATCH * NPIX, 256>>>(kf, kd, ksc, 256);
    qrows_kernel<<<BATCH * CV,   256>>>(vf, vd, vsc, 4096);
    // E = Q.K^T
    gemm_s8_kernel<0, 128, 64><<<dim3(32, 64, 4), 256, SME>>>(nullptr, f_b, g_b, h_b);
    // softmax -> P digits
    softmax_kernel<<<dim3(NPIX, BATCH), 256>>>();
    // out = P.V^T  (64m x 128n: P re-read x4 instead of x8)
    gemm_s8_kernel<1, 64, 128><<<dim3(64, 4, 4), 256, SME>>>(out, f_b, g_b, h_b);
}

// round 11
// speedup vs baseline: 7.1242x; 1.0237x over previous
#include <cuda_runtime.h>
#include <cuda_bf16.h>
#include <cstdint>

// ---------------------------------------------------------------------------
// SAGAN self-attention, B=4, C=512, H=W=64 (N=4096), fp32 in/out.
// R11: same int8 tensor-core kernels as R10 (mma.sync m16n8k32 s8.s8.s32,
// 16-bit fixed-point rowwise quant, 3-product scheme), but kernel_launch now
// builds a forked multi-stream DAG inside graph capture:
//   - wsplit || (xtrans ; qrows Xt)
//   - proj
//   - qrows Q || qrows K || qrows V
//   - 4 per-batch chains  E(b) -> softmax(b) -> PV(b)  on 4 streams
// so the DRAM-bound softmax/quant kernels overlap the tensor-bound GEMMs.
// ---------------------------------------------------------------------------

#define BATCH 4
#define NPIX  4096
#define CIN   512
#define CV    512
#define SME   98304    // 2 x 48KB chunk buffers; epilogue reuses < 35KB

// fp32 staging
__device__ __align__(16) float  g_Xtf[(size_t)BATCH * NPIX * 512];
__device__ __align__(16) float  g_Qf [(size_t)BATCH * NPIX * 256];
__device__ __align__(16) float  g_Kf [(size_t)BATCH * NPIX * 256];
__device__ __align__(16) float  g_Vf [(size_t)BATCH * CV   * 4096];
__device__ __align__(16) float  g_E  [(size_t)BATCH * NPIX * NPIX];
// digit buffers: rows stored [d1 K | d2 K]
__device__ __align__(16) int8_t g_Wd [(size_t)1024 * 1024];
__device__ __align__(16) int8_t g_Xtd[(size_t)BATCH * NPIX * 1024];
__device__ __align__(16) int8_t g_Qd [(size_t)BATCH * NPIX * 512];
__device__ __align__(16) int8_t g_Kd [(size_t)BATCH * NPIX * 512];
__device__ __align__(16) int8_t g_Vd [(size_t)BATCH * CV   * 8192];
__device__ __align__(16) int8_t g_Pd [(size_t)BATCH * NPIX * 8192];
// row scales
__device__ float g_Wsc [1024];
__device__ float g_Xsc [(size_t)BATCH * NPIX];
__device__ float g_Qsc [(size_t)BATCH * NPIX];
__device__ float g_Ksc [(size_t)BATCH * NPIX];
__device__ float g_Vsc [(size_t)BATCH * CV];
__device__ float g_Psc [(size_t)BATCH * NPIX];

#define SWZ128(x) ((x) ^ (((x) >> 3) & 0x70))

__device__ __forceinline__ uint32_t smem_u32(const void* p) {
    uint32_t a;
    asm("{ .reg .u64 t; cvta.to.shared.u64 t, %1; cvt.u32.u64 %0, t; }"
        : "=r"(a) : "l"(p));
    return a;
}
__device__ __forceinline__ void cp16(uint32_t saddr, const void* g) {
    asm volatile("cp.async.cg.shared.global [%0], [%1], 16;"
                 :: "r"(saddr), "l"(g));
}
#define CP_COMMIT() asm volatile("cp.async.commit_group;" ::: "memory")
#define CP_WAIT(n)  asm volatile("cp.async.wait_group %0;" :: "n"(n) : "memory")

__device__ __forceinline__ void ldm_x4(uint32_t* r, uint32_t addr) {
    asm volatile("ldmatrix.sync.aligned.m8n8.x4.shared.b16 {%0,%1,%2,%3}, [%4];"
                 : "=r"(r[0]), "=r"(r[1]), "=r"(r[2]), "=r"(r[3]) : "r"(addr));
}
__device__ __forceinline__ void mma_s8(int* c, const uint32_t* a,
                                       const uint32_t* b) {
    asm volatile(
        "mma.sync.aligned.m16n8k32.row.col.s32.s8.s8.s32 "
        "{%0,%1,%2,%3}, {%4,%5,%6,%7}, {%8,%9}, {%0,%1,%2,%3};"
        : "+r"(c[0]), "+r"(c[1]), "+r"(c[2]), "+r"(c[3])
        : "r"(a[0]), "r"(a[1]), "r"(a[2]), "r"(a[3]), "r"(b[0]), "r"(b[1]));
}
// fp32 combine: |accA| < 2^27 -> rel err ~2^-24, negligible vs 5e-4 budget
__device__ __forceinline__ float comb2(int hi, int mid) {
    return fmaf((float)hi, 65536.f, (float)mid * 256.f);
}

// ---------------------------------------------------------------------------
// transpose x -> g_Xtf [b][n][512] fp32
// ---------------------------------------------------------------------------
__global__ __launch_bounds__(256)
void xtrans_kernel(const float* __restrict__ x)
{
    __shared__ float ts[32][33];
    const int tx = threadIdx.x, ty = threadIdx.y;
    const int n0 = blockIdx.x * 32, c0 = blockIdx.y * 32, b = blockIdx.z;
#pragma unroll
    for (int i = 0; i < 4; i++)
        ts[ty + i * 8][tx] =
            x[((size_t)(b * CIN + c0 + ty + i * 8)) * NPIX + n0 + tx];
    __syncthreads();
#pragma unroll
    for (int i = 0; i < 4; i++) {
        const int n = n0 + ty + i * 8;
        g_Xtf[((size_t)(b * NPIX + n)) * 512 + c0 + tx] = ts[tx][ty + i * 8];
    }
}

// ---------------------------------------------------------------------------
// qrows: per-row 16-bit fixed-point quantization.
// src row [K] fp32 -> dst row [d1 K | d2 K] s8, sc[row] = rowmax/32512.
// ---------------------------------------------------------------------------
__global__ __launch_bounds__(256)
void qrows_kernel(const float* __restrict__ src, int8_t* __restrict__ dst,
                  float* __restrict__ sc, int K)
{
    __shared__ float red[8];
    const int r = blockIdx.x, t = threadIdx.x;
    const float* row = src + (size_t)r * K;

    float mx = 0.f;
    for (int k = t; k < K; k += 256) mx = fmaxf(mx, fabsf(row[k]));
#pragma unroll
    for (int o = 16; o > 0; o >>= 1) mx = fmaxf(mx, __shfl_xor_sync(~0u, mx, o));
    if ((t & 31) == 0) red[t >> 5] = mx;
    __syncthreads();
    if (t < 8) {
        float v = red[t];
        v = fmaxf(v, __shfl_xor_sync(0xffu, v, 1));
        v = fmaxf(v, __shfl_xor_sync(0xffu, v, 2));
        v = fmaxf(v, __shfl_xor_sync(0xffu, v, 4));
        red[t] = v;
    }
    __syncthreads();
    mx = red[0];
    const float q = (mx > 0.f) ? 32512.f / mx : 0.f;
    if (t == 0) sc[r] = mx * (1.f / 32512.f);

    int8_t* d1p = dst + (size_t)r * (2 * K);
    for (int k = t; k < K; k += 256) {
        int d  = __float2int_rn(row[k] * q);
        int d1 = (d + 128) >> 8;
        d1p[k]     = (int8_t)d1;
        d1p[K + k] = (int8_t)(d - (d1 << 8));
    }
}

// ---------------------------------------------------------------------------
// Unified int8 GEMM, tile-shape templated. D[m][n] = sum_k A[m][k] B[n][k],
// rows [d1 K|d2 K] s8. CTA MT x NT (MT+NT == 192 -> 48KB chunk, 2x buffered,
// occupancy 2). 8 warps, warp tile 32x32. accA = d1e1 (w 65536),
// accB = d1e2+d2e1 (w 256); d2e2 dropped. Batch = blockIdx.z + bOfs.
// WHICH=0 (128x64): A=g_Kd(j), B=g_Qd(i) -> g_E fp32
// WHICH=1 (64x128): A=g_Pd(i), B=g_Vd(c) -> out fp32
// WHICH=2 (128x64): A=g_Wd(o), B=g_Xtd(n) -> +bias -> g_Qf/g_Kf/g_Vf
// ---------------------------------------------------------------------------
template <int WHICH, int MT, int NT>
__global__ void __launch_bounds__(256, 2)
gemm_s8_kernel(float* __restrict__ Dout,
               const float* __restrict__ fb, const float* __restrict__ gb,
               const float* __restrict__ hb, int bOfs)
{
    static_assert(MT + NT == 192, "chunk sized for 48KB");
    extern __shared__ __align__(1024) char smc[];
    const uint32_t smb = smem_u32(smc);

    const int t   = threadIdx.x;
    const int wid = t >> 5;
    const int lt  = t & 31;
    const int mBase = blockIdx.x * MT;
    const int nBase = blockIdx.y * NT;
    const int b     = blockIdx.z + bOfs;

    const int8_t* Ab; const int8_t* Bb;
    const float* sAv; const float* sBv;
    int kchunks;
    if (WHICH == 0) {
        Ab = g_Kd + (size_t)b * NPIX * 512;
        Bb = g_Qd + (size_t)b * NPIX * 512;
        sAv = g_Ksc + (size_t)b * NPIX;
        sBv = g_Qsc + (size_t)b * NPIX;
        kchunks = 2;
    } else if (WHICH == 1) {
        Ab = g_Pd + (size_t)b * NPIX * 8192;
        Bb = g_Vd + (size_t)b * CV * 8192;
        sAv = g_Psc + (size_t)b * NPIX;
        sBv = g_Vsc + (size_t)b * CV;
        kchunks = 32;
    } else {
        Ab = g_Wd;
        Bb = g_Xtd + (size_t)b * NPIX * 1024;
        sAv = g_Wsc;
        sBv = g_Xsc + (size_t)b * NPIX;
        kchunks = 4;
    }
    const int Koff    = kchunks * 128;   // digit-2 offset within a row
    const int strideA = Koff * 2;        // bytes per row

    // 8 warps: (MT/32) m-warps x (NT/32) n-warps, warp tile 32x32
    constexpr int NW = NT / 32;
    const int m0 = (wid / NW) * 32;
    const int n0 = (wid % NW) * 32;
    const int aRow  = (lt & 7) + ((lt >> 3) & 1) * 8;
    const int aByte = ((lt >> 4) & 1) * 16;
    const int bRow  = (lt & 7) + ((lt >> 4) & 1) * 8;
    const int bByte = ((lt >> 3) & 1) * 16;

    int accA[2][4][4], accB[2][4][4];
#pragma unroll
    for (int i = 0; i < 2; i++)
#pragma unroll
        for (int j = 0; j < 4; j++)
#pragma unroll
            for (int r = 0; r < 4; r++) { accA[i][j][r] = 0; accB[i][j][r] = 0; }

    // chunk layout: A1 @0, A2 @MT*128, B1 @2*MT*128, B2 @2*MT*128+NT*128
    constexpr uint32_t OA2 = (uint32_t)MT * 128u;
    constexpr uint32_t OB1 = 2u * MT * 128u;
    constexpr uint32_t OB2 = OB1 + (uint32_t)NT * 128u;
    auto load_chunk = [&](int cc, int buf) {
        const uint32_t base = (uint32_t)buf * 49152u;
        const int k0 = cc * 128;
#pragma unroll
        for (int i = 0; i < MT / 32; i++) {
            int u = t + i * 256;
            int row = u >> 3, c16 = u & 7;
            uint32_t sw = SWZ128(row * 128 + c16 * 16);
            const int8_t* gp = Ab + (size_t)(mBase + row) * strideA + k0 + c16 * 16;
            cp16(smb + base + sw, gp);
            cp16(smb + base + OA2 + sw, gp + Koff);
        }
#pragma unroll
        for (int i = 0; i < NT / 32; i++) {
            int u = t + i * 256;
            int row = u >> 3, c16 = u & 7;
            uint32_t sw = SWZ128(row * 128 + c16 * 16);
            const int8_t* gp = Bb + (size_t)(nBase + row) * strideA + k0 + c16 * 16;
            cp16(smb + base + OB1 + sw, gp);
            cp16(smb + base + OB2 + sw, gp + Koff);
        }
        CP_COMMIT();
    };

    load_chunk(0, 0);
    for (int cc = 0; cc < kchunks; cc++) {
        if (cc + 1 < kchunks) { load_chunk(cc + 1, (cc + 1) & 1); CP_WAIT(1); }
        else                  { CP_WAIT(0); }
        __syncthreads();

        const uint32_t ba  = (uint32_t)(cc & 1) * 49152u;
        const uint32_t oA1 = ba, oA2 = ba + OA2;
        const uint32_t oB1 = ba + OB1, oB2 = ba + OB2;

#pragma unroll
        for (int kq = 0; kq < 4; kq++) {
            const int kb = kq * 32;                // 32 bytes = k32 step
            uint32_t a1[2][4], a2[2][4], b1[2][4], b2[2][4];
#pragma unroll
            for (int im = 0; im < 2; im++) {
                uint32_t sw = SWZ128((m0 + im * 16 + aRow) * 128 + kb + aByte);
                ldm_x4(a1[im], smb + oA1 + sw);
                ldm_x4(a2[im], smb + oA2 + sw);
            }
#pragma unroll
            for (int jp = 0; jp < 2; jp++) {
                uint32_t sw = SWZ128((n0 + jp * 16 + bRow) * 128 + kb + bByte);
                ldm_x4(b1[jp], smb + oB1 + sw);
                ldm_x4(b2[jp], smb + oB2 + sw);
            }
#pragma unroll
            for (int im = 0; im < 2; im++)
#pragma unroll
                for (int jn = 0; jn < 4; jn++) {
                    const uint32_t* e1 = &b1[jn >> 1][(jn & 1) * 2];
                    const uint32_t* e2 = &b2[jn >> 1][(jn & 1) * 2];
                    mma_s8(accA[im][jn], a1[im], e1);
                    mma_s8(accB[im][jn], a1[im], e2);
                    mma_s8(accB[im][jn], a2[im], e1);
                }
        }
        __syncthreads();
    }

    const int cr   = lt >> 2;
    const int ccol = 2 * (lt & 3);
    constexpr int SCT = MT + 4;

    if (WHICH <= 1) {
        float* sC = (float*)smc;   // [NT n][MT+4 m]
#pragma unroll
        for (int im = 0; im < 2; im++) {
            const int m = m0 + im * 16 + cr;
            const float sa0 = sAv[mBase + m], sa1 = sAv[mBase + m + 8];
#pragma unroll
            for (int jn = 0; jn < 4; jn++) {
                const int n = n0 + jn * 8 + ccol;
                const float sb0 = sBv[nBase + n], sb1 = sBv[nBase + n + 1];
                sC[n * SCT + m]           = comb2(accA[im][jn][0], accB[im][jn][0]) * (sa0 * sb0);
                sC[(n + 1) * SCT + m]     = comb2(accA[im][jn][1], accB[im][jn][1]) * (sa0 * sb1);
                sC[n * SCT + m + 8]       = comb2(accA[im][jn][2], accB[im][jn][2]) * (sa1 * sb0);
                sC[(n + 1) * SCT + m + 8] = comb2(accA[im][jn][3], accB[im][jn][3]) * (sa1 * sb1);
            }
        }
        __syncthreads();
        float* Db = (WHICH == 0) ? g_E + (size_t)b * NPIX * NPIX
                                 : Dout + (size_t)b * CV * NPIX;
        constexpr int M4 = MT / 4;
#pragma unroll
        for (int i = 0; i < (NT * M4) / 256; i++) {
            int idx = t + i * 256;
            int n = idx / M4, m4 = (idx % M4) * 4;
            float4 v = *(const float4*)(sC + n * SCT + m4);
            *(float4*)(Db + (size_t)(nBase + n) * NPIX + mBase + m4) = v;
        }
    } else {
        const float* bsel; int o0;
        if (mBase < 256)      { bsel = fb; o0 = mBase; }
        else if (mBase < 512) { bsel = gb; o0 = mBase - 256; }
        else                  { bsel = hb; o0 = mBase - 512; }

        if (mBase < 512) {
            float* sC = (float*)smc;   // [NT n][MT+4 m]
#pragma unroll
            for (int im = 0; im < 2; im++) {
                const int m = m0 + im * 16 + cr;
                const float sa0 = sAv[mBase + m], sa1 = sAv[mBase + m + 8];
                const float bi0 = bsel[o0 + m], bi1 = bsel[o0 + m + 8];
#pragma unroll
                for (int jn = 0; jn < 4; jn++) {
                    const int n = n0 + jn * 8 + ccol;
                    const float sb0 = sBv[nBase + n], sb1 = sBv[nBase + n + 1];
                    sC[n * SCT + m]           = comb2(accA[im][jn][0], accB[im][jn][0]) * (sa0 * sb0) + bi0;
                    sC[(n + 1) * SCT + m]     = comb2(accA[im][jn][1], accB[im][jn][1]) * (sa0 * sb1) + bi0;
                    sC[n * SCT + m + 8]       = comb2(accA[im][jn][2], accB[im][jn][2]) * (sa1 * sb0) + bi1;
                    sC[(n + 1) * SCT + m + 8] = comb2(accA[im][jn][3], accB[im][jn][3]) * (sa1 * sb1) + bi1;
                }
            }
            __syncthreads();
            float* dst = (mBase < 256) ? g_Qf : g_Kf;
            const int oc0 = mBase & 255;   // 0 or 128
#pragma unroll
            for (int i = 0; i < 8; i++) {
                int idx = t + i * 256;
                int n = idx >> 5, m4 = (idx & 31) << 2;
                float4 v = *(const float4*)(sC + n * SCT + m4);
                *(float4*)(dst + ((size_t)(b * NPIX + nBase + n)) * 256 + oc0 + m4) = v;
            }
        } else {
            float* sC = (float*)smc;   // [MT m][NT+4 n]
#pragma unroll
            for (int im = 0; im < 2; im++) {
                const int m = m0 + im * 16 + cr;
                const float sa0 = sAv[mBase + m], sa1 = sAv[mBase + m + 8];
                const float bi0 = bsel[o0 + m], bi1 = bsel[o0 + m + 8];
#pragma unroll
                for (int jn = 0; jn < 4; jn++) {
                    const int n = n0 + jn * 8 + ccol;
                    const float sb0 = sBv[nBase + n], sb1 = sBv[nBase + n + 1];
                    sC[m * 68 + n]           = comb2(accA[im][jn][0], accB[im][jn][0]) * (sa0 * sb0) + bi0;
                    sC[m * 68 + n + 1]       = comb2(accA[im][jn][1], accB[im][jn][1]) * (sa0 * sb1) + bi0;
                    sC[(m + 8) * 68 + n]     = comb2(accA[im][jn][2], accB[im][jn][2]) * (sa1 * sb0) + bi1;
                    sC[(m + 8) * 68 + n + 1] = comb2(accA[im][jn][3], accB[im][jn][3]) * (sa1 * sb1) + bi1;
                }
            }
            __syncthreads();
#pragma unroll
            for (int i = 0; i < 8; i++) {
                int idx = t + i * 256;
                int m = idx >> 4, n4 = (idx & 15) << 2;
                float4 v = *(const float4*)(sC + m * 68 + n4);
                *(float4*)(g_Vf + ((size_t)(b * CV + o0 + m)) * 4096 + nBase + n4) = v;
            }
        }
    }
}

// ---------------------------------------------------------------------------
// softmax: row softmax over E -> P digits (d = rint(e * 32512)), scale.
// One CTA per row i of batch (blockIdx.y + bOfs).
// ---------------------------------------------------------------------------
__global__ __launch_bounds__(256)
void softmax_kernel(int bOfs)
{
    __shared__ float red[8];
    const int i = blockIdx.x, b = blockIdx.y + bOfs, t = threadIdx.x;
    const float* row = g_E + ((size_t)(b * NPIX + i)) * NPIX;

    float4 v[4];
#pragma unroll
    for (int r = 0; r < 4; r++) v[r] = ((const float4*)row)[t + r * 256];

    float m = -1e30f;
#pragma unroll
    for (int r = 0; r < 4; r++)
        m = fmaxf(m, fmaxf(fmaxf(v[r].x, v[r].y), fmaxf(v[r].z, v[r].w)));
#pragma unroll
    for (int o = 16; o > 0; o >>= 1) m = fmaxf(m, __shfl_xor_sync(~0u, m, o));
    if ((t & 31) == 0) red[t >> 5] = m;
    __syncthreads();
    if (t < 8) {
        float x2 = red[t];
        x2 = fmaxf(x2, __shfl_xor_sync(0xffu, x2, 1));
        x2 = fmaxf(x2, __shfl_xor_sync(0xffu, x2, 2));
        x2 = fmaxf(x2, __shfl_xor_sync(0xffu, x2, 4));
        red[t] = x2;
    }
    __syncthreads();
    m = red[0];
    __syncthreads();

    float e[16];
    float ssum = 0.f;
#pragma unroll
    for (int r = 0; r < 4; r++) {
        e[r * 4 + 0] = __expf(v[r].x - m);
        e[r * 4 + 1] = __expf(v[r].y - m);
        e[r * 4 + 2] = __expf(v[r].z - m);
        e[r * 4 + 3] = __expf(v[r].w - m);
        ssum += (e[r*4+0] + e[r*4+1]) + (e[r*4+2] + e[r*4+3]);
    }
#pragma unroll
    for (int o = 16; o > 0; o >>= 1) ssum += __shfl_xor_sync(~0u, ssum, o);
    if ((t & 31) == 0) red[t >> 5] = ssum;
    __syncthreads();
    if (t < 8) {
        float x2 = red[t];
        x2 += __shfl_xor_sync(0xffu, x2, 1);
        x2 += __shfl_xor_sync(0xffu, x2, 2);
        x2 += __shfl_xor_sync(0xffu, x2, 4);
        red[t] = x2;
    }
    __syncthreads();
    const float inv = 1.f / red[0];
    if (t == 0) g_Psc[(size_t)b * NPIX + i] = inv * (1.f / 32512.f);

    int8_t* pb = g_Pd + ((size_t)(b * NPIX + i)) * 8192;
#pragma unroll
    for (int r = 0; r < 4; r++) {
        const int j0 = (t + r * 256) * 4;
        char d1v[4], d2v[4];
#pragma unroll
        for (int k = 0; k < 4; k++) {
            int d  = __float2int_rn(e[r * 4 + k] * 32512.f);
            int d1 = (d + 128) >> 8;
            d1v[k] = (char)d1;
            d2v[k] = (char)(d - (d1 << 8));
        }
        *(char4*)(pb + j0)        = make_char4(d1v[0], d1v[1], d1v[2], d1v[3]);
        *(char4*)(pb + 4096 + j0) = make_char4(d2v[0], d2v[1], d2v[2], d2v[3]);
    }
}

// ---------------------------------------------------------------------------
extern "C" void kernel_launch(void* const* d_in, const int* in_sizes, int n_in,
                              void* d_out, int out_size)
{
    const float* x   = (const float*)d_in[0];
    const float* f_w = (const float*)d_in[1];
    const float* f_b = (const float*)d_in[2];
    const float* g_w = (const float*)d_in[3];
    const float* g_b = (const float*)d_in[4];
    const float* h_w = (const float*)d_in[5];
    const float* h_b = (const float*)d_in[6];
    float* out = (float*)d_out;
    (void)in_sizes; (void)n_in; (void)out_size;

    // one-time setup (runs during the uncaptured correctness call)
    static bool inited = false;
    static cudaStream_t s1, s2, s3;
    static cudaEvent_t eRoot, eW, eP, eK, eV, eAll, eJ1, eJ2, eJ3;
    if (!inited) {
        cudaStreamCreateWithFlags(&s1, cudaStreamNonBlocking);
        cudaStreamCreateWithFlags(&s2, cudaStreamNonBlocking);
        cudaStreamCreateWithFlags(&s3, cudaStreamNonBlocking);
        cudaEventCreateWithFlags(&eRoot, cudaEventDisableTiming);
        cudaEventCreateWithFlags(&eW,    cudaEventDisableTiming);
        cudaEventCreateWithFlags(&eP,    cudaEventDisableTiming);
        cudaEventCreateWithFlags(&eK,    cudaEventDisableTiming);
        cudaEventCreateWithFlags(&eV,    cudaEventDisableTiming);
        cudaEventCreateWithFlags(&eAll,  cudaEventDisableTiming);
        cudaEventCreateWithFlags(&eJ1,   cudaEventDisableTiming);
        cudaEventCreateWithFlags(&eJ2,   cudaEventDisableTiming);
        cudaEventCreateWithFlags(&eJ3,   cudaEventDisableTiming);
        cudaFuncSetAttribute((const void*)gemm_s8_kernel<0, 128, 64>,
                             cudaFuncAttributeMaxDynamicSharedMemorySize, SME);
        cudaFuncSetAttribute((const void*)gemm_s8_kernel<1, 64, 128>,
                             cudaFuncAttributeMaxDynamicSharedMemorySize, SME);
        cudaFuncSetAttribute((const void*)gemm_s8_kernel<2, 128, 64>,
                             cudaFuncAttributeMaxDynamicSharedMemorySize, SME);
        inited = true;
    }

    int8_t* wd; float* wsc; float* xtf; int8_t* xtd; float* xsc;
    cudaGetSymbolAddress((void**)&wd,  g_Wd);
    cudaGetSymbolAddress((void**)&wsc, g_Wsc);
    cudaGetSymbolAddress((void**)&xtf, g_Xtf);
    cudaGetSymbolAddress((void**)&xtd, g_Xtd);
    cudaGetSymbolAddress((void**)&xsc, g_Xsc);
    float* qf; float* kf; float* vf;
    int8_t* qd; int8_t* kd; int8_t* vd;
    float* qsc; float* ksc; float* vsc;
    cudaGetSymbolAddress((void**)&qf, g_Qf);  cudaGetSymbolAddress((void**)&kf, g_Kf);
    cudaGetSymbolAddress((void**)&vf, g_Vf);
    cudaGetSymbolAddress((void**)&qd, g_Qd);  cudaGetSymbolAddress((void**)&kd, g_Kd);
    cudaGetSymbolAddress((void**)&vd, g_Vd);
    cudaGetSymbolAddress((void**)&qsc, g_Qsc); cudaGetSymbolAddress((void**)&ksc, g_Ksc);
    cudaGetSymbolAddress((void**)&vsc, g_Vsc);

    cudaStream_t s0 = 0;   // harness captures the default stream

    // fork: weight quant on s1, x-transpose + pixel quant on s0
    cudaEventRecord(eRoot, s0);
    cudaStreamWaitEvent(s1, eRoot, 0);
    qrows_kernel<<<256, 256, 0, s1>>>(f_w, wd,              wsc,       512);
    qrows_kernel<<<256, 256, 0, s1>>>(g_w, wd + 256 * 1024, wsc + 256, 512);
    qrows_kernel<<<512, 256, 0, s1>>>(h_w, wd + 512 * 1024, wsc + 512, 512);
    cudaEventRecord(eW, s1);

    xtrans_kernel<<<dim3(NPIX / 32, CIN / 32, BATCH), dim3(32, 8), 0, s0>>>(x);
    qrows_kernel<<<BATCH * NPIX, 256, 0, s0>>>(xtf, xtd, xsc, 512);
    cudaStreamWaitEvent(s0, eW, 0);

    // proj GEMM -> fp32 Q/K/V
    gemm_s8_kernel<2, 128, 64><<<dim3(8, 64, 4), 256, SME, s0>>>(nullptr, f_b, g_b, h_b, 0);
    cudaEventRecord(eP, s0);

    // fork: Q on s0, K on s1, V on s2
    cudaStreamWaitEvent(s1, eP, 0);
    cudaStreamWaitEvent(s2, eP, 0);
    qrows_kernel<<<BATCH * NPIX, 256, 0, s1>>>(kf, kd, ksc, 256);
    cudaEventRecord(eK, s1);
    qrows_kernel<<<BATCH * CV,   256, 0, s2>>>(vf, vd, vsc, 4096);
    cudaEventRecord(eV, s2);
    qrows_kernel<<<BATCH * NPIX, 256, 0, s0>>>(qf, qd, qsc, 256);
    cudaStreamWaitEvent(s0, eK, 0);
    cudaStreamWaitEvent(s0, eV, 0);
    cudaEventRecord(eAll, s0);

    // 4 per-batch chains: E(b) -> softmax(b) -> PV(b)
    cudaStreamWaitEvent(s1, eAll, 0);
    cudaStreamWaitEvent(s2, eAll, 0);
    cudaStreamWaitEvent(s3, eAll, 0);
    cudaStream_t chains[4] = {s0, s1, s2, s3};
    for (int b = 0; b < BATCH; b++) {
        cudaStream_t s = chains[b];
        gemm_s8_kernel<0, 128, 64><<<dim3(32, 64, 1), 256, SME, s>>>(nullptr, f_b, g_b, h_b, b);
        softmax_kernel<<<dim3(NPIX, 1), 256, 0, s>>>(b);
        gemm_s8_kernel<1, 64, 128><<<dim3(64, 4, 1), 256, SME, s>>>(out, f_b, g_b, h_b, b);
    }

    // join
    cudaEventRecord(eJ1, s1);
    cudaEventRecord(eJ2, s2);
    cudaEventRecord(eJ3, s3);
    cudaStreamWaitEvent(s0, eJ1, 0);
    cudaStreamWaitEvent(s0, eJ2, 0);
    cudaStreamWaitEvent(s0, eJ3, 0);
}